// round 15
// baseline (speedup 1.0000x reference)
#include <cuda_runtime.h>
#include <cuda_bf16.h>
#include <cuda_fp16.h>
#include <cstdint>
#include <math.h>

#define TT 32
#define BBATCH 32
#define HH 512
#define SS 400
#define VV 50000
#define EXTV 50050
#define TB 1024  // TT*BBATCH
#define NBLK 128
#define NBX_V 391   // vocab n-tiles

// ---------------- scratch (static device arrays; no allocation) ----------------
__device__ float g_x[TB * HH];
__device__ float g_xw[2048 * TB];       // W_ih1 @ x^T : [gate_row][t*32+b]
__device__ float g_out[TB * HH];
__device__ float g_call[TB * HH];
__device__ float g_h1P[2 * HH * BBATCH];  // parity-buffered layer-1 h PAIR-PACKED [p][J/2][b][2]
__device__ float g_h2P[2 * HH * BBATCH];
__device__ float g_c1f[BBATCH * HH];
__device__ float g_c2f[BBATCH * HH];
__device__ float g_gamma[TB * HH];
__device__ float g_attn[TB * SS];
__device__ float g_cat2[TB * 2 * HH];
__device__ float g_hatt[TB * HH];
__device__ float g_pgen[TB];
__device__ float g_rinv[TB];
__device__ float g_sumpart[TB * NBX_V];
__device__ __half g_elog[(size_t)TB * VV];           // exp(logits) fp16, 100 MB
__device__ __nv_bfloat16 g_hattb[TB * HH];
__device__ __nv_bfloat16 g_wvb[(size_t)VV * HH];
__device__ __nv_bfloat16 g_wi1p[2048 * 3 * HH];
__device__ __nv_bfloat16 g_xp[TB * 3 * HH];
__device__ __nv_bfloat16 g_cat2p[TB * 3 * 2 * HH];
__device__ __nv_bfloat16 g_wop[HH * 3 * 2 * HH];
__device__ unsigned g_cnt1[8];
__device__ unsigned g_cnt2;
__device__ unsigned g_gen;

__device__ __forceinline__ uint32_t smem_u32(const void* p) {
    uint32_t a;
    asm("{ .reg .u64 t; cvta.to.shared.u64 t, %1; cvt.u32.u64 %0, t; }" : "=r"(a) : "l"(p));
    return a;
}

#define FMA2(acc, w, h) \
    asm("fma.rn.f32x2 %0, %1, %2, %0;" : "+l"(acc) : "l"(w), "l"(h))

__device__ __forceinline__ float hadd2(unsigned long long a) {
    return __uint_as_float((unsigned)a) + __uint_as_float((unsigned)(a >> 32));
}

// ---------------- embedding ----------------
__global__ void k_embed(const int* __restrict__ ids, const float* __restrict__ emb) {
    int gi = blockIdx.x * blockDim.x + threadIdx.x;
    int r = gi >> 7, e4 = gi & 127;
    int id = ids[r];
    if (id >= VV) id = 1;   // UNK
    float4 v = *(const float4*)(emb + (size_t)id * HH + e4 * 4);
    *(float4*)(g_x + (size_t)r * HH + e4 * 4) = v;
}

// ---------------- fp32 -> bf16 convert ----------------
__global__ void k_cvt(const float* __restrict__ src, __nv_bfloat16* __restrict__ dst, int n4) {
    int i = blockIdx.x * blockDim.x + threadIdx.x;
    if (i >= n4) return;
    float4 v = ((const float4*)src)[i];
    __nv_bfloat162 a = __floats2bfloat162_rn(v.x, v.y);
    __nv_bfloat162 b = __floats2bfloat162_rn(v.z, v.w);
    ((__nv_bfloat162*)dst)[i * 2]     = a;
    ((__nv_bfloat162*)dst)[i * 2 + 1] = b;
}

// ---------------- split-bf16 pack: mode 0 -> [hi|hi|lo], mode 1 -> [hi|lo|hi] ----------------
__global__ void k_pack3(const float* __restrict__ src, __nv_bfloat16* __restrict__ dst,
                        int K, int total, int mode) {
    int i = blockIdx.x * blockDim.x + threadIdx.x;
    if (i >= total) return;
    int r = i / K, k = i - r * K;
    float v = src[i];
    __nv_bfloat16 hi = __float2bfloat16(v);
    __nv_bfloat16 lo = __float2bfloat16(v - __bfloat162float(hi));
    __nv_bfloat16* row = dst + (size_t)r * 3 * K;
    row[k] = hi;
    if (mode == 0) { row[K + k] = hi; row[2 * K + k] = lo; }
    else           { row[K + k] = lo; row[2 * K + k] = hi; }
}

// ---------------- transpose h0 into pair-packed parity buffers ----------------
__global__ void k_tr(const float* __restrict__ h0) {
    int i = blockIdx.x * blockDim.x + threadIdx.x;
    if (i >= 32768) return;
    int layer = i >> 14, rem = i & 16383;
    int J = rem >> 5, b = rem & 31;
    float v = h0[layer * 16384 + b * 512 + J];
    int idx = (J >> 1) * 64 + b * 2 + (J & 1);
    if (layer) g_h2P[idx] = v;            // parity 0
    else       g_h1P[16384 + idx] = v;    // parity 1
}

// ---------------- persistent 2-layer LSTM: tree gridbar ----------------
__device__ __forceinline__ float sigf(float x) { return 1.0f / (1.0f + __expf(-x)); }
__device__ __forceinline__ float tanhff(float x) { return 1.0f - 2.0f / (__expf(2.0f * x) + 1.0f); }

// Two-level arrival tree: 8 groups of 16 blocks, then 1 of 8. Resets are
// ordered before the gen increment every next-step arrival waits on.
__device__ __forceinline__ void gridbar(int tid, int bid) {
    __syncthreads();
    if (tid == 0) {
        __threadfence();
        unsigned gen = *(volatile unsigned*)&g_gen;
        int grp = bid >> 4;
        unsigned o = atomicAdd(&g_cnt1[grp], 1u);
        if (o == 15u) {
            atomicExch(&g_cnt1[grp], 0u);
            unsigned o2 = atomicAdd(&g_cnt2, 1u);
            if (o2 == 7u) {
                atomicExch(&g_cnt2, 0u);
                __threadfence();
                atomicAdd(&g_gen, 1u);
            } else {
                while (*(volatile unsigned*)&g_gen == gen) { }
            }
        } else {
            while (*(volatile unsigned*)&g_gen == gen) { }
        }
        __threadfence();
    }
    __syncthreads();
}

// smem weight layout: [kp][16 rows][2] floats. h layout: [kp][32 b][2] floats.
__global__ void __launch_bounds__(512, 1) k_persist(
    const float* __restrict__ Whh1, const float* __restrict__ Wih2,
    const float* __restrict__ Whh2,
    const float* __restrict__ bih, const float* __restrict__ bhh,
    const float* __restrict__ c0)
{
    extern __shared__ float sm[];
    float* wT1 = sm;                         // [256 kp][16][2]   32 KB
    float* wT2 = sm + 512 * 16;              // [512 kp][16][2]   64 KB
    float* hs  = sm + 512 * 16 + 1024 * 16;  // [512 kp][32][2]  128 KB
    float* gpart = hs + 16384;               // alias kp 256..319 (layer-2-only region)

    __shared__ float c1s[4][32], c2s[4][32], bsum[2][16];

    const int tid = threadIdx.x;
    const int bid = blockIdx.x;
    const int w = tid >> 5, l = tid & 31;
    const int rg = w >> 3;          // 0..1
    const int oct = w & 7;          // 0..7
    const int ejj = tid >> 5, eb = tid & 31, eJ = bid * 4 + ejj;  // epilogue coords (tid<128)

    // ---- one-time: weight slices into smem (pair-interleaved) ----
    #pragma unroll 1
    for (int r = 0; r < 16; r++) {
        int g = r & 3, jj = r >> 2;
        int G = g * 512 + bid * 4 + jj;
        int k = tid;  // 0..511
        int kp = k >> 1, kq = k & 1;
        wT1[kp * 32 + r * 2 + kq]          = Whh1[(size_t)G * 512 + k];
        wT2[kp * 32 + r * 2 + kq]          = Wih2[(size_t)G * 512 + k];
        wT2[(256 + kp) * 32 + r * 2 + kq]  = Whh2[(size_t)G * 512 + k];
    }
    if (tid < 32) {
        int layer = tid >> 4, r = tid & 15;
        int g = r & 3, jj = r >> 2;
        int G = layer * 2048 + g * 512 + bid * 4 + jj;
        bsum[layer][r] = bih[G] + bhh[G];
    }
    if (tid < 128) {
        c1s[ejj][eb] = c0[eb * 512 + eJ];
        c2s[ejj][eb] = c0[16384 + eb * 512 + eJ];
    }
    // pre-stage: hs kp 0..255 = h1 init (parity 1)
    {
        float4* dst4 = (float4*)hs;
        const float4* s1 = (const float4*)(g_h1P + 16384);
        #pragma unroll
        for (int j = 0; j < 8; j++) dst4[tid + j * 512] = s1[tid + j * 512];
    }
    __syncthreads();

    for (int t = 0; t < TT; t++) {
        const int pw1 = t & 1;
        const int ph2r = t & 1;
        const int ph2w = (t & 1) ^ 1;

        // prefetch xw for this step's layer-1 epilogue (xw is constant -> safe)
        float xwreg[4];
        if (tid < 128) {
            #pragma unroll
            for (int g = 0; g < 4; g++)
                xwreg[g] = __ldg(&g_xw[(size_t)(g * 512 + eJ) * 1024 + t * 32 + eb]);
        }

        // ---- layer 1: kp in [oct*32, oct*32+32) ----
        {
            unsigned long long a0 = 0, a1 = 0, a2 = 0, a3 = 0, a4 = 0, a5 = 0, a6 = 0, a7 = 0;
            const float* wp = wT1 + rg * 16;
            const int kp0 = oct * 32;
            #pragma unroll 8
            for (int kp = kp0; kp < kp0 + 32; kp++) {
                const float* wk = wp + kp * 32;
                ulonglong2 w01 = *(const ulonglong2*)(wk);
                ulonglong2 w23 = *(const ulonglong2*)(wk + 4);
                ulonglong2 w45 = *(const ulonglong2*)(wk + 8);
                ulonglong2 w67 = *(const ulonglong2*)(wk + 12);
                unsigned long long hp = *(const unsigned long long*)(hs + kp * 64 + l * 2);
                FMA2(a0, w01.x, hp); FMA2(a1, w01.y, hp);
                FMA2(a2, w23.x, hp); FMA2(a3, w23.y, hp);
                FMA2(a4, w45.x, hp); FMA2(a5, w45.y, hp);
                FMA2(a6, w67.x, hp); FMA2(a7, w67.y, hp);
            }
            float* gp = gpart + oct * 512 + rg * 8 * 32 + l;
            gp[0] = hadd2(a0);   gp[32] = hadd2(a1);  gp[64] = hadd2(a2);  gp[96] = hadd2(a3);
            gp[128] = hadd2(a4); gp[160] = hadd2(a5); gp[192] = hadd2(a6); gp[224] = hadd2(a7);
        }
        __syncthreads();
        if (tid < 128) {
            float gv[4];
            #pragma unroll
            for (int g = 0; g < 4; g++) {
                int r = ejj * 4 + g;
                float s = bsum[0][r] + xwreg[g];
                #pragma unroll
                for (int o = 0; o < 8; o++) s += gpart[o * 512 + r * 32 + eb];
                gv[g] = s;
            }
            float cn = sigf(gv[1]) * c1s[ejj][eb] + sigf(gv[0]) * tanhff(gv[2]);
            float hn = sigf(gv[3]) * tanhff(cn);
            c1s[ejj][eb] = cn;
            g_h1P[pw1 * 16384 + (eJ >> 1) * 64 + eb * 2 + (eJ & 1)] = hn;
        }
        gridbar(tid, bid);

        // ---- stage: kp 0..255 <- h1P[pw1]; kp 256..511 <- h2P[ph2r] ----
        {
            float4* dst4 = (float4*)hs;
            const float4* s1 = (const float4*)(g_h1P + pw1 * 16384);
            const float4* s2 = (const float4*)(g_h2P + ph2r * 16384);
            #pragma unroll
            for (int j = 0; j < 8; j++)  dst4[tid + j * 512] = __ldcg(s1 + tid + j * 512);
            #pragma unroll
            for (int j = 0; j < 8; j++)  dst4[tid + (j + 8) * 512] = __ldcg(s2 + tid + j * 512);
        }
        __syncthreads();

        // ---- layer 2: kp in [oct*64, oct*64+64) over 512 pairs ----
        {
            unsigned long long a0 = 0, a1 = 0, a2 = 0, a3 = 0, a4 = 0, a5 = 0, a6 = 0, a7 = 0;
            const float* wp = wT2 + rg * 16;
            const int kp0 = oct * 64;
            #pragma unroll 8
            for (int kp = kp0; kp < kp0 + 64; kp++) {
                const float* wk = wp + kp * 32;
                ulonglong2 w01 = *(const ulonglong2*)(wk);
                ulonglong2 w23 = *(const ulonglong2*)(wk + 4);
                ulonglong2 w45 = *(const ulonglong2*)(wk + 8);
                ulonglong2 w67 = *(const ulonglong2*)(wk + 12);
                unsigned long long hp = *(const unsigned long long*)(hs + kp * 64 + l * 2);
                FMA2(a0, w01.x, hp); FMA2(a1, w01.y, hp);
                FMA2(a2, w23.x, hp); FMA2(a3, w23.y, hp);
                FMA2(a4, w45.x, hp); FMA2(a5, w45.y, hp);
                FMA2(a6, w67.x, hp); FMA2(a7, w67.y, hp);
            }
            __syncthreads();   // all hs reads done before gpart alias overwrite
            float* gp = gpart + oct * 512 + rg * 8 * 32 + l;
            gp[0] = hadd2(a0);   gp[32] = hadd2(a1);  gp[64] = hadd2(a2);  gp[96] = hadd2(a3);
            gp[128] = hadd2(a4); gp[160] = hadd2(a5); gp[192] = hadd2(a6); gp[224] = hadd2(a7);
        }
        __syncthreads();
        if (tid < 128) {
            float gv[4];
            #pragma unroll
            for (int g = 0; g < 4; g++) {
                int r = ejj * 4 + g;
                float s = bsum[1][r];
                #pragma unroll
                for (int o = 0; o < 8; o++) s += gpart[o * 512 + r * 32 + eb];
                gv[g] = s;
            }
            float cn = sigf(gv[1]) * c2s[ejj][eb] + sigf(gv[0]) * tanhff(gv[2]);
            float hn = sigf(gv[3]) * tanhff(cn);
            c2s[ejj][eb] = cn;
            g_h2P[ph2w * 16384 + (eJ >> 1) * 64 + eb * 2 + (eJ & 1)] = hn;
            int row = t * 32 + eb;
            g_out[(size_t)row * 512 + eJ] = hn;
            g_cat2[(size_t)row * 1024 + 512 + eJ] = hn;
            g_call[(size_t)row * 512 + eJ] = cn;
        }
        __syncthreads();
        // hs kp 0..255 keep h1(t) for next step's layer 1
    }

    if (tid < 128) {
        g_c1f[eb * 512 + eJ] = c1s[ejj][eb];
        g_c2f[eb * 512 + eJ] = c2s[ejj][eb];
    }
}

// ---------------- generic tiled fp32 GEMM (attention path) ----------------
__global__ void k_gemm(int M, int N, int K,
                       const float* __restrict__ A, int lda, long long sA,
                       const float* __restrict__ B, int ldbn, int ldbk, long long sB,
                       const float* __restrict__ bias,
                       float* __restrict__ C, int ldc, long long sC, int act) {
    A += (size_t)blockIdx.z * sA;
    B += (size_t)blockIdx.z * sB;
    C += (size_t)blockIdx.z * sC;
    __shared__ float As[16][64];
    __shared__ float Bs[16][64];
    int tid = threadIdx.x;
    int tx = tid & 15, ty = tid >> 4;
    int m0 = blockIdx.y * 64, n0 = blockIdx.x * 64;
    int ar = tid >> 2, ak = (tid & 3) * 4;
    float acc[4][4] = {};

    for (int k0 = 0; k0 < K; k0 += 16) {
        float4 av = make_float4(0.f, 0.f, 0.f, 0.f);
        if (m0 + ar < M) av = *(const float4*)(A + (size_t)(m0 + ar) * lda + k0 + ak);
        As[ak + 0][ar] = av.x; As[ak + 1][ar] = av.y;
        As[ak + 2][ar] = av.z; As[ak + 3][ar] = av.w;
        if (ldbk == 1) {
            float4 bq = make_float4(0.f, 0.f, 0.f, 0.f);
            if (n0 + ar < N) bq = *(const float4*)(B + (size_t)(n0 + ar) * ldbn + k0 + ak);
            Bs[ak + 0][ar] = bq.x; Bs[ak + 1][ar] = bq.y;
            Bs[ak + 2][ar] = bq.z; Bs[ak + 3][ar] = bq.w;
        } else {
            #pragma unroll
            for (int e = tid; e < 1024; e += 256) {
                int n = e & 63, kk = e >> 6;
                float v = 0.f;
                if (n0 + n < N) v = B[(size_t)(n0 + n) * ldbn + (size_t)(k0 + kk) * ldbk];
                Bs[kk][n] = v;
            }
        }
        __syncthreads();
        #pragma unroll
        for (int kk = 0; kk < 16; kk++) {
            float4 a = *(const float4*)(&As[kk][ty * 4]);
            float4 bq = *(const float4*)(&Bs[kk][tx * 4]);
            acc[0][0] += a.x * bq.x; acc[0][1] += a.x * bq.y; acc[0][2] += a.x * bq.z; acc[0][3] += a.x * bq.w;
            acc[1][0] += a.y * bq.x; acc[1][1] += a.y * bq.y; acc[1][2] += a.y * bq.z; acc[1][3] += a.y * bq.w;
            acc[2][0] += a.z * bq.x; acc[2][1] += a.z * bq.y; acc[2][2] += a.z * bq.z; acc[2][3] += a.z * bq.w;
            acc[3][0] += a.w * bq.x; acc[3][1] += a.w * bq.y; acc[3][2] += a.w * bq.z; acc[3][3] += a.w * bq.w;
        }
        __syncthreads();
    }

    #pragma unroll
    for (int i = 0; i < 4; i++) {
        int m = m0 + ty * 4 + i;
        if (m >= M) continue;
        #pragma unroll
        for (int jc = 0; jc < 4; jc++) {
            int n = n0 + tx * 4 + jc;
            if (n >= N) continue;
            float v = acc[i][jc];
            if (bias) v += bias[n];
            if (act == 1) v = tanhf(v);
            C[(size_t)m * ldc + n] = v;
        }
    }
}

// ---------------- generalized bf16 HMMA GEMM (register prefetch, static smem) ----------------
#define VPAD 72

__global__ void __launch_bounds__(256) k_hgemm(
    const __nv_bfloat16* __restrict__ A,   // [M, K] bf16 row-major
    const __nv_bfloat16* __restrict__ B,   // [>=nbound, K] bf16 row-major
    const float* __restrict__ bias,
    float* __restrict__ C,                 // [M, ldc] fp32 (unused when eout set)
    int K, int ldc, int nbound, int act,
    float* __restrict__ sumpart, int nbx,
    __nv_bfloat16* __restrict__ bf16out,   // optional bf16 copy of C
    __half* __restrict__ eout)             // optional: store exp(v) as fp16, skip C
{
    __shared__ __nv_bfloat16 As[128 * VPAD];
    __shared__ __nv_bfloat16 Bs[128 * VPAD];
    __shared__ float srow[128 * 17];

    const int tid = threadIdx.x;
    const int wid = tid >> 5, lane = tid & 31;
    const int m0 = blockIdx.y * 128, n0 = blockIdx.x * 128;
    const int wr = wid >> 2, wc = wid & 3;

    float acc[4][4][4] = {};
    const uint32_t sA = smem_u32(As), sB = smem_u32(Bs);
    const int nkc = K >> 6;

    uint4 pa[4], pb[4];
    #pragma unroll
    for (int it = 0; it < 4; it++) {
        int idx = tid + it * 256;
        int row = idx >> 3, qv = idx & 7;
        pa[it] = *(const uint4*)(A + (size_t)(m0 + row) * K + qv * 8);
        int n = n0 + row;
        pb[it] = make_uint4(0u, 0u, 0u, 0u);
        if (n < nbound) pb[it] = *(const uint4*)(B + (size_t)n * K + qv * 8);
    }

    for (int kc = 0; kc < nkc; kc++) {
        #pragma unroll
        for (int it = 0; it < 4; it++) {
            int idx = tid + it * 256;
            int row = idx >> 3, qv = idx & 7;
            *(uint4*)(As + row * VPAD + qv * 8) = pa[it];
            *(uint4*)(Bs + row * VPAD + qv * 8) = pb[it];
        }
        __syncthreads();
        if (kc + 1 < nkc) {
            #pragma unroll
            for (int it = 0; it < 4; it++) {
                int idx = tid + it * 256;
                int row = idx >> 3, qv = idx & 7;
                pa[it] = *(const uint4*)(A + (size_t)(m0 + row) * K + (kc + 1) * 64 + qv * 8);
                int n = n0 + row;
                pb[it] = make_uint4(0u, 0u, 0u, 0u);
                if (n < nbound) pb[it] = *(const uint4*)(B + (size_t)n * K + (kc + 1) * 64 + qv * 8);
            }
        }

        #pragma unroll
        for (int ks = 0; ks < 4; ks++) {
            uint32_t af[4][4];
            uint32_t bf[4][2];
            #pragma unroll
            for (int fm = 0; fm < 4; fm++) {
                int row = wr * 64 + fm * 16 + (lane & 15);
                int col = ks * 16 + ((lane >> 4) << 3);
                uint32_t addr = sA + (row * VPAD + col) * 2;
                asm volatile("ldmatrix.sync.aligned.m8n8.x4.shared.b16 {%0,%1,%2,%3}, [%4];"
                    : "=r"(af[fm][0]), "=r"(af[fm][1]), "=r"(af[fm][2]), "=r"(af[fm][3])
                    : "r"(addr));
            }
            #pragma unroll
            for (int fn = 0; fn < 4; fn++) {
                int row = wc * 32 + fn * 8 + (lane & 7);
                int col = ks * 16 + (((lane >> 3) & 1) << 3);
                uint32_t addr = sB + (row * VPAD + col) * 2;
                asm volatile("ldmatrix.sync.aligned.m8n8.x2.shared.b16 {%0,%1}, [%2];"
                    : "=r"(bf[fn][0]), "=r"(bf[fn][1]) : "r"(addr));
            }
            #pragma unroll
            for (int fm = 0; fm < 4; fm++) {
                #pragma unroll
                for (int fn = 0; fn < 4; fn++) {
                    asm volatile(
                        "mma.sync.aligned.m16n8k16.row.col.f32.bf16.bf16.f32 "
                        "{%0,%1,%2,%3}, {%4,%5,%6,%7}, {%8,%9}, {%0,%1,%2,%3};"
                        : "+f"(acc[fm][fn][0]), "+f"(acc[fm][fn][1]),
                          "+f"(acc[fm][fn][2]), "+f"(acc[fm][fn][3])
                        : "r"(af[fm][0]), "r"(af[fm][1]), "r"(af[fm][2]), "r"(af[fm][3]),
                          "r"(bf[fn][0]), "r"(bf[fn][1]));
                }
            }
        }
        __syncthreads();
    }

    int gr = lane >> 2, gc = (lane & 3) * 2;
    int slot = wc * 4 + (lane & 3);
    #pragma unroll
    for (int fm = 0; fm < 4; fm++) {
        int lr0 = wr * 64 + fm * 16 + gr;
        int r0 = m0 + lr0;
        float es0 = 0.f, es1 = 0.f;
        if (eout) {
            __half* erow0 = eout + (size_t)r0 * ldc;
            __half* erow1 = eout + (size_t)(r0 + 8) * ldc;
            #pragma unroll
            for (int fn = 0; fn < 4; fn++) {
                int c = n0 + wc * 32 + fn * 8 + gc;
                if (c + 1 < nbound) {
                    float b0 = bias[c], b1 = bias[c + 1];
                    float e0 = __expf(acc[fm][fn][0] + b0);
                    float e1 = __expf(acc[fm][fn][1] + b1);
                    float e2 = __expf(acc[fm][fn][2] + b0);
                    float e3 = __expf(acc[fm][fn][3] + b1);
                    erow0[c] = __float2half(e0); erow0[c + 1] = __float2half(e1);
                    erow1[c] = __float2half(e2); erow1[c + 1] = __float2half(e3);
                    es0 += e0 + e1;
                    es1 += e2 + e3;
                } else if (c < nbound) {
                    float b0 = bias[c];
                    float e0 = __expf(acc[fm][fn][0] + b0);
                    float e2 = __expf(acc[fm][fn][2] + b0);
                    erow0[c] = __float2half(e0);
                    erow1[c] = __float2half(e2);
                    es0 += e0; es1 += e2;
                }
            }
            srow[lr0 * 17 + slot] = es0;
            srow[(lr0 + 8) * 17 + slot] = es1;
        } else {
            float* crow0 = C + (size_t)r0 * ldc;
            float* crow1 = C + (size_t)(r0 + 8) * ldc;
            #pragma unroll
            for (int fn = 0; fn < 4; fn++) {
                int c = n0 + wc * 32 + fn * 8 + gc;
                if (c + 1 < nbound) {
                    float b0 = bias ? bias[c] : 0.f, b1 = bias ? bias[c + 1] : 0.f;
                    float v0 = acc[fm][fn][0] + b0, v1 = acc[fm][fn][1] + b1;
                    float v2 = acc[fm][fn][2] + b0, v3 = acc[fm][fn][3] + b1;
                    if (act == 1) { v0 = tanhf(v0); v1 = tanhf(v1); v2 = tanhf(v2); v3 = tanhf(v3); }
                    crow0[c] = v0; crow0[c + 1] = v1;
                    crow1[c] = v2; crow1[c + 1] = v3;
                    if (bf16out) {
                        bf16out[(size_t)r0 * ldc + c]           = __float2bfloat16(v0);
                        bf16out[(size_t)r0 * ldc + c + 1]       = __float2bfloat16(v1);
                        bf16out[(size_t)(r0 + 8) * ldc + c]     = __float2bfloat16(v2);
                        bf16out[(size_t)(r0 + 8) * ldc + c + 1] = __float2bfloat16(v3);
                    }
                } else if (c < nbound) {
                    float b0 = bias ? bias[c] : 0.f;
                    float v0 = acc[fm][fn][0] + b0, v2 = acc[fm][fn][2] + b0;
                    if (act == 1) { v0 = tanhf(v0); v2 = tanhf(v2); }
                    crow0[c] = v0; crow1[c] = v2;
                    if (bf16out) {
                        bf16out[(size_t)r0 * ldc + c]       = __float2bfloat16(v0);
                        bf16out[(size_t)(r0 + 8) * ldc + c] = __float2bfloat16(v2);
                    }
                }
            }
        }
    }
    if (sumpart) {
        __syncthreads();
        if (tid < 128) {
            float s = 0.f;
            #pragma unroll
            for (int i = 0; i < 16; i++) s += srow[tid * 17 + i];
            sumpart[(size_t)(m0 + tid) * nbx + blockIdx.x] = s;
        }
    }
}

// ---------------- row-sum reduce -> 1/sum ----------------
__global__ void k_rowsum() {
    int r = blockIdx.x, tid = threadIdx.x;
    __shared__ float red[128];
    float s = 0.f;
    for (int i = tid; i < NBX_V; i += 128) s += g_sumpart[(size_t)r * NBX_V + i];
    red[tid] = s; __syncthreads();
    for (int o = 64; o > 0; o >>= 1) { if (tid < o) red[tid] += red[tid + o]; __syncthreads(); }
    if (tid == 0) g_rinv[r] = 1.f / red[0];
}

// ---------------- attention softmax over S=400 ----------------
__global__ void k_attnsoftmax() {
    int r = blockIdx.x, tid = threadIdx.x;
    __shared__ float vals[SS];
    __shared__ float red[128];
    float m = -1e30f;
    for (int s = tid; s < SS; s += 128) { float v = g_attn[(size_t)r * SS + s]; vals[s] = v; m = fmaxf(m, v); }
    red[tid] = m; __syncthreads();
    for (int o = 64; o > 0; o >>= 1) { if (tid < o) red[tid] = fmaxf(red[tid], red[tid + o]); __syncthreads(); }
    m = red[0]; __syncthreads();
    float sum = 0.f;
    for (int s = tid; s < SS; s += 128) { float e = __expf(vals[s] - m); vals[s] = e; sum += e; }
    red[tid] = sum; __syncthreads();
    for (int o = 64; o > 0; o >>= 1) { if (tid < o) red[tid] += red[tid + o]; __syncthreads(); }
    float inv = 1.f / red[0];
    for (int s = tid; s < SS; s += 128) g_attn[(size_t)r * SS + s] = vals[s] * inv;
}

// ---------------- p_gen ----------------
__global__ void k_pgen(const float* __restrict__ Wg, const float* __restrict__ bg) {
    int warp = threadIdx.x >> 5, lane = threadIdx.x & 31;
    int r = blockIdx.x * 8 + warp;
    float acc = 0.f;
    for (int j = lane; j < 512; j += 32) {
        acc += g_hatt[(size_t)r * HH + j] * Wg[j]
             + g_out [(size_t)r * HH + j] * Wg[512 + j]
             + g_call[(size_t)r * HH + j] * Wg[1024 + j]
             + g_x   [(size_t)r * HH + j] * Wg[1536 + j];
    }
    for (int o = 16; o > 0; o >>= 1) acc += __shfl_down_sync(0xffffffffu, acc, o);
    if (lane == 0) g_pgen[r] = 1.f / (1.f + expf(-(acc + bg[0])));
}

// ---------------- base scores (from fp16 exp-logits) ----------------
__global__ void k_scores(float* __restrict__ out) {
    int r = blockIdx.y;
    int v0 = (blockIdx.x * blockDim.x + threadIdx.x) * 4;
    float pg = g_pgen[r], inv = g_rinv[r];
    float* orow = out + (size_t)r * EXTV;
    const __half* erow = g_elog + (size_t)r * VV;
    #pragma unroll
    for (int i = 0; i < 4; i++) {
        int v = v0 + i;
        if (v >= EXTV) return;
        float sc;
        if (v < VV) {
            float p = __half2float(erow[v]) * inv;
            sc = __logf(p * pg + 1e-10f);
        } else {
            sc = __logf(1e-10f);
        }
        orow[v] = sc;
    }
}

// ---------------- copy fixup (last-write-wins) ----------------
__global__ void k_fixup(const int* __restrict__ src, float* __restrict__ out) {
    int r = blockIdx.x, b = r & 31;
    __shared__ int sid[SS];
    int s = threadIdx.x;
    if (s < SS) sid[s] = src[s * BBATCH + b];
    __syncthreads();
    if (s >= SS) return;
    int v = sid[s];
    for (int s2 = s + 1; s2 < SS; s2++) if (sid[s2] == v) return;
    float pg = g_pgen[r];
    float a = g_attn[(size_t)r * SS + s];
    float pv = 0.f;
    if (v < VV) pv = __half2float(g_elog[(size_t)r * VV + v]) * g_rinv[r];
    out[(size_t)r * EXTV + v] = __logf(pv * pg + a * (1.f - pg) + 1e-10f);
}

// ---------------- final h, c ----------------
__global__ void k_hc(float* __restrict__ out) {
    int i = blockIdx.x * blockDim.x + threadIdx.x;
    float* dst = out + (size_t)TB * EXTV;
    int b = i >> 9, J = i & 511;
    int idx = (J >> 1) * 64 + b * 2 + (J & 1);
    dst[i]          = g_h1P[16384 + idx];   // final h1: parity 1 (t=31)
    dst[16384 + i]  = g_h2P[idx];           // final h2: parity 0
    dst[32768 + i]  = g_c1f[i];
    dst[49152 + i]  = g_c2f[i];
}

// ---------------- launch ----------------
extern "C" void kernel_launch(void* const* d_in, const int* in_sizes, int n_in,
                              void* d_out, int out_size) {
    const int*   ids = (const int*)d_in[0];
    const int*   src = (const int*)d_in[1];
    const float* h0  = (const float*)d_in[2];
    const float* c0  = (const float*)d_in[3];
    const float* ctx = (const float*)d_in[4];
    int base = (in_sizes[5] <= 4) ? 6 : 5;
    const float* emb = (const float*)d_in[base + 0];
    const float* Wih = (const float*)d_in[base + 1];
    const float* bih = (const float*)d_in[base + 2];
    const float* Whh = (const float*)d_in[base + 3];
    const float* bhh = (const float*)d_in[base + 4];
    const float* Wa  = (const float*)d_in[base + 5];
    const float* ba  = (const float*)d_in[base + 6];
    const float* Wo  = (const float*)d_in[base + 7];
    const float* bo  = (const float*)d_in[base + 8];
    const float* Wv  = (const float*)d_in[base + 9];
    const float* bv  = (const float*)d_in[base + 10];
    const float* Wg  = (const float*)d_in[base + 11];
    const float* bg  = (const float*)d_in[base + 12];
    float* out = (float*)d_out;

    float *px, *pxw, *pout, *pgamma, *pattn, *pcat2, *phatt, *psum;
    __half* pelog;
    __nv_bfloat16 *phattb, *pwvb, *pwi1p, *pxp, *pcat2p, *pwop;
    cudaGetSymbolAddress((void**)&px,      g_x);
    cudaGetSymbolAddress((void**)&pxw,     g_xw);
    cudaGetSymbolAddress((void**)&pout,    g_out);
    cudaGetSymbolAddress((void**)&pgamma,  g_gamma);
    cudaGetSymbolAddress((void**)&pattn,   g_attn);
    cudaGetSymbolAddress((void**)&pcat2,   g_cat2);
    cudaGetSymbolAddress((void**)&phatt,   g_hatt);
    cudaGetSymbolAddress((void**)&pelog,   g_elog);
    cudaGetSymbolAddress((void**)&psum,    g_sumpart);
    cudaGetSymbolAddress((void**)&phattb,  g_hattb);
    cudaGetSymbolAddress((void**)&pwvb,    g_wvb);
    cudaGetSymbolAddress((void**)&pwi1p,   g_wi1p);
    cudaGetSymbolAddress((void**)&pxp,     g_xp);
    cudaGetSymbolAddress((void**)&pcat2p,  g_cat2p);
    cudaGetSymbolAddress((void**)&pwop,    g_wop);

    const int SMEM_PERSIST = (512 * 16 + 1024 * 16 + 1024 * 32) * 4;  // 229376 B
    cudaFuncSetAttribute(k_persist, cudaFuncAttributeMaxDynamicSharedMemorySize, SMEM_PERSIST);

    // 1. embedding + weight converts/packs + h0 transpose
    k_embed<<<512, 256>>>(ids, emb);
    k_cvt<<<25000, 256>>>(Wv, pwvb, VV * HH / 4);
    k_pack3<<<4096, 256>>>(Wih, pwi1p, HH, 2048 * HH, 0);      // [hi|hi|lo]
    k_pack3<<<2048, 256>>>(px, pxp, HH, TB * HH, 1);           // [hi|lo|hi]
    k_pack3<<<2048, 256>>>(Wo, pwop, 2 * HH, HH * 2 * HH, 0);  // [hi|hi|lo]
    k_tr<<<64, 512>>>(h0);

    // 2. xw hoist via split-bf16 HMMA (K=1536)
    k_hgemm<<<dim3(8, 16), 256>>>(pwi1p, pxp, nullptr, pxw,
                                  3 * HH, TB, TB, 0, nullptr, 0, nullptr, nullptr);

    // 3. persistent 2-layer LSTM (tree gridbar, xw prefetch)
    k_persist<<<NBLK, 512, SMEM_PERSIST>>>(Whh, Wih + 2048 * 512, Whh + 2048 * 512,
                                           bih, bhh, c0);

    // 4. gamma = out @ Wa^T + ba (fp32)
    k_gemm<<<dim3(8, 16, 1), 256>>>(TB, HH, HH, pout, HH, 0,
                                    Wa, HH, 1, 0, ba, pgamma, HH, 0, 0);

    // 5. attn logits per b: gamma @ contexts[b]^T (fp32)
    k_gemm<<<dim3(7, 1, 32), 256>>>(BBATCH, SS, HH,
                                    pgamma, BBATCH * HH, HH,
                                    ctx, HH, 1, (long long)SS * HH,
                                    nullptr, pattn, BBATCH * SS, SS, 0);

    // 6. softmax over s
    k_attnsoftmax<<<TB, 128>>>();

    // 7. c_t = attn @ contexts[b] (fp32)
    k_gemm<<<dim3(8, 1, 32), 256>>>(BBATCH, HH, SS,
                                    pattn, BBATCH * SS, SS,
                                    ctx, 1, HH, (long long)SS * HH,
                                    nullptr, pcat2, BBATCH * 2 * HH, 2 * HH, 0);

    // 8. h_att = tanh(cat2 @ Wo^T + bo) via split-bf16 HMMA; bf16 copy fused
    k_pack3<<<4096, 256>>>(pcat2, pcat2p, 2 * HH, TB * 2 * HH, 1);  // [hi|lo|hi]
    k_hgemm<<<dim3(4, 8), 256>>>(pcat2p, pwop, bo, phatt,
                                 3 * 2 * HH, HH, HH, 1, nullptr, 0, phattb, nullptr);

    // 9. p_gen
    k_pgen<<<128, 256>>>(Wg, bg);

    // 10. vocab: fused exp(logits)->fp16 + row-sum partials
    k_hgemm<<<dim3(NBX_V, 8), 256>>>(phattb, pwvb, bv, nullptr,
                                     HH, VV, VV, 0, psum, NBX_V, nullptr, pelog);
    k_rowsum<<<TB, 128>>>();

    // 11. scores + copy fixup
    k_scores<<<dim3(49, TB, 1), 256>>>(out);
    k_fixup<<<TB, 512>>>(src, out);

    // 12. final h, c
    k_hc<<<64, 256>>>(out);
}

// round 16
// speedup vs baseline: 1.0326x; 1.0326x over previous
#include <cuda_runtime.h>
#include <cuda_bf16.h>
#include <cuda_fp16.h>
#include <cstdint>
#include <math.h>

#define TT 32
#define BBATCH 32
#define HH 512
#define SS 400
#define VV 50000
#define EXTV 50050
#define TB 1024  // TT*BBATCH
#define NBLK 128
#define NBX_V 391   // vocab n-tiles

// ---------------- scratch (static device arrays; no allocation) ----------------
__device__ float g_x[TB * HH];
__device__ float g_xw[2048 * TB];       // W_ih1 @ x^T : [gate_row][t*32+b]
__device__ float g_out[TB * HH];
__device__ float g_call[TB * HH];
__device__ float g_h1P[2 * HH * BBATCH];  // parity-buffered layer-1 h PAIR-PACKED [p][J/2][b][2]
__device__ float g_h2P[2 * HH * BBATCH];
__device__ float g_c1f[BBATCH * HH];
__device__ float g_c2f[BBATCH * HH];
__device__ float g_gamma[TB * HH];
__device__ float g_attn[TB * SS];
__device__ float g_cat2[TB * 2 * HH];
__device__ float g_hatt[TB * HH];
__device__ float g_pgen[TB];
__device__ float g_rinv[TB];
__device__ float g_sumpart[TB * NBX_V];
__device__ __half g_elog[(size_t)TB * VV];           // exp(logits) fp16, 100 MB
__device__ __nv_bfloat16 g_hattb[TB * HH];
__device__ __nv_bfloat16 g_wvb[(size_t)VV * HH];
__device__ __nv_bfloat16 g_wi1p[2048 * 3 * HH];
__device__ __nv_bfloat16 g_xp[TB * 3 * HH];
__device__ __nv_bfloat16 g_cat2p[TB * 3 * 2 * HH];
__device__ __nv_bfloat16 g_wop[HH * 3 * 2 * HH];
__device__ unsigned g_barcnt;
__device__ unsigned g_bargen;

__device__ __forceinline__ uint32_t smem_u32(const void* p) {
    uint32_t a;
    asm("{ .reg .u64 t; cvta.to.shared.u64 t, %1; cvt.u32.u64 %0, t; }" : "=r"(a) : "l"(p));
    return a;
}

#define FMA2(acc, w, h) \
    asm("fma.rn.f32x2 %0, %1, %2, %0;" : "+l"(acc) : "l"(w), "l"(h))

__device__ __forceinline__ float hadd2(unsigned long long a) {
    return __uint_as_float((unsigned)a) + __uint_as_float((unsigned)(a >> 32));
}

// ---------------- embedding ----------------
__global__ void k_embed(const int* __restrict__ ids, const float* __restrict__ emb) {
    int gi = blockIdx.x * blockDim.x + threadIdx.x;
    int r = gi >> 7, e4 = gi & 127;
    int id = ids[r];
    if (id >= VV) id = 1;   // UNK
    float4 v = *(const float4*)(emb + (size_t)id * HH + e4 * 4);
    *(float4*)(g_x + (size_t)r * HH + e4 * 4) = v;
}

// ---------------- fp32 -> bf16 convert ----------------
__global__ void k_cvt(const float* __restrict__ src, __nv_bfloat16* __restrict__ dst, int n4) {
    int i = blockIdx.x * blockDim.x + threadIdx.x;
    if (i >= n4) return;
    float4 v = ((const float4*)src)[i];
    __nv_bfloat162 a = __floats2bfloat162_rn(v.x, v.y);
    __nv_bfloat162 b = __floats2bfloat162_rn(v.z, v.w);
    ((__nv_bfloat162*)dst)[i * 2]     = a;
    ((__nv_bfloat162*)dst)[i * 2 + 1] = b;
}

// ---------------- split-bf16 pack: mode 0 -> [hi|hi|lo], mode 1 -> [hi|lo|hi] ----------------
__global__ void k_pack3(const float* __restrict__ src, __nv_bfloat16* __restrict__ dst,
                        int K, int total, int mode) {
    int i = blockIdx.x * blockDim.x + threadIdx.x;
    if (i >= total) return;
    int r = i / K, k = i - r * K;
    float v = src[i];
    __nv_bfloat16 hi = __float2bfloat16(v);
    __nv_bfloat16 lo = __float2bfloat16(v - __bfloat162float(hi));
    __nv_bfloat16* row = dst + (size_t)r * 3 * K;
    row[k] = hi;
    if (mode == 0) { row[K + k] = hi; row[2 * K + k] = lo; }
    else           { row[K + k] = lo; row[2 * K + k] = hi; }
}

// ---------------- transpose h0 into pair-packed parity buffers ----------------
__global__ void k_tr(const float* __restrict__ h0) {
    int i = blockIdx.x * blockDim.x + threadIdx.x;
    if (i >= 32768) return;
    int layer = i >> 14, rem = i & 16383;
    int J = rem >> 5, b = rem & 31;
    float v = h0[layer * 16384 + b * 512 + J];
    int idx = (J >> 1) * 64 + b * 2 + (J & 1);
    if (layer) g_h2P[idx] = v;            // parity 0
    else       g_h1P[16384 + idx] = v;    // parity 1
}

// ---------------- persistent 2-layer LSTM (R13 config: flat atomic gridbar) ----------------
__device__ __forceinline__ float sigf(float x) { return 1.0f / (1.0f + __expf(-x)); }
__device__ __forceinline__ float tanhff(float x) { return 1.0f - 2.0f / (__expf(2.0f * x) + 1.0f); }

__device__ __forceinline__ void gridbar(int tid) {
    __syncthreads();
    if (tid == 0) {
        __threadfence();
        unsigned gen = *(volatile unsigned*)&g_bargen;
        unsigned old = atomicAdd(&g_barcnt, 1u);
        if (old == NBLK - 1) {
            atomicExch(&g_barcnt, 0u);
            __threadfence();
            atomicAdd(&g_bargen, 1u);
        } else {
            while (*(volatile unsigned*)&g_bargen == gen) { }
        }
        __threadfence();
    }
    __syncthreads();
}

// smem weight layout: [kp][16 rows][2] floats. h layout: [kp][32 b][2] floats.
__global__ void __launch_bounds__(512, 1) k_persist(
    const float* __restrict__ Whh1, const float* __restrict__ Wih2,
    const float* __restrict__ Whh2,
    const float* __restrict__ bih, const float* __restrict__ bhh,
    const float* __restrict__ c0)
{
    extern __shared__ float sm[];
    float* wT1 = sm;                         // [256 kp][16][2]   32 KB
    float* wT2 = sm + 512 * 16;              // [512 kp][16][2]   64 KB
    float* hs  = sm + 512 * 16 + 1024 * 16;  // [512 kp][32][2]  128 KB
    float* gpart = hs + 16384;               // alias kp 256..319 (layer-2-only region)

    __shared__ float c1s[4][32], c2s[4][32], bsum[2][16];

    const int tid = threadIdx.x;
    const int bid = blockIdx.x;
    const int w = tid >> 5, l = tid & 31;
    const int rg = w >> 3;          // 0..1
    const int oct = w & 7;          // 0..7
    const int ejj = tid >> 5, eb = tid & 31, eJ = bid * 4 + ejj;  // epilogue coords (tid<128)

    #pragma unroll 1
    for (int r = 0; r < 16; r++) {
        int g = r & 3, jj = r >> 2;
        int G = g * 512 + bid * 4 + jj;
        int k = tid;  // 0..511
        int kp = k >> 1, kq = k & 1;
        wT1[kp * 32 + r * 2 + kq]          = Whh1[(size_t)G * 512 + k];
        wT2[kp * 32 + r * 2 + kq]          = Wih2[(size_t)G * 512 + k];
        wT2[(256 + kp) * 32 + r * 2 + kq]  = Whh2[(size_t)G * 512 + k];
    }
    if (tid < 32) {
        int layer = tid >> 4, r = tid & 15;
        int g = r & 3, jj = r >> 2;
        int G = layer * 2048 + g * 512 + bid * 4 + jj;
        bsum[layer][r] = bih[G] + bhh[G];
    }
    if (tid < 128) {
        c1s[ejj][eb] = c0[eb * 512 + eJ];
        c2s[ejj][eb] = c0[16384 + eb * 512 + eJ];
    }
    {
        float4* dst4 = (float4*)hs;
        const float4* s1 = (const float4*)(g_h1P + 16384);
        #pragma unroll
        for (int j = 0; j < 8; j++) dst4[tid + j * 512] = s1[tid + j * 512];
    }
    __syncthreads();

    for (int t = 0; t < TT; t++) {
        const int pw1 = t & 1;
        const int ph2r = t & 1;
        const int ph2w = (t & 1) ^ 1;

        // prefetch xw for this step's layer-1 epilogue (xw is constant -> safe)
        float xwreg[4];
        if (tid < 128) {
            #pragma unroll
            for (int g = 0; g < 4; g++)
                xwreg[g] = __ldg(&g_xw[(size_t)(g * 512 + eJ) * 1024 + t * 32 + eb]);
        }

        // ---- layer 1: kp in [oct*32, oct*32+32) ----
        {
            unsigned long long a0 = 0, a1 = 0, a2 = 0, a3 = 0, a4 = 0, a5 = 0, a6 = 0, a7 = 0;
            const float* wp = wT1 + rg * 16;
            const int kp0 = oct * 32;
            #pragma unroll 8
            for (int kp = kp0; kp < kp0 + 32; kp++) {
                const float* wk = wp + kp * 32;
                ulonglong2 w01 = *(const ulonglong2*)(wk);
                ulonglong2 w23 = *(const ulonglong2*)(wk + 4);
                ulonglong2 w45 = *(const ulonglong2*)(wk + 8);
                ulonglong2 w67 = *(const ulonglong2*)(wk + 12);
                unsigned long long hp = *(const unsigned long long*)(hs + kp * 64 + l * 2);
                FMA2(a0, w01.x, hp); FMA2(a1, w01.y, hp);
                FMA2(a2, w23.x, hp); FMA2(a3, w23.y, hp);
                FMA2(a4, w45.x, hp); FMA2(a5, w45.y, hp);
                FMA2(a6, w67.x, hp); FMA2(a7, w67.y, hp);
            }
            float* gp = gpart + oct * 512 + rg * 8 * 32 + l;
            gp[0] = hadd2(a0);   gp[32] = hadd2(a1);  gp[64] = hadd2(a2);  gp[96] = hadd2(a3);
            gp[128] = hadd2(a4); gp[160] = hadd2(a5); gp[192] = hadd2(a6); gp[224] = hadd2(a7);
        }
        __syncthreads();
        if (tid < 128) {
            float gv[4];
            #pragma unroll
            for (int g = 0; g < 4; g++) {
                int r = ejj * 4 + g;
                float s = bsum[0][r] + xwreg[g];
                #pragma unroll
                for (int o = 0; o < 8; o++) s += gpart[o * 512 + r * 32 + eb];
                gv[g] = s;
            }
            float cn = sigf(gv[1]) * c1s[ejj][eb] + sigf(gv[0]) * tanhff(gv[2]);
            float hn = sigf(gv[3]) * tanhff(cn);
            c1s[ejj][eb] = cn;
            g_h1P[pw1 * 16384 + (eJ >> 1) * 64 + eb * 2 + (eJ & 1)] = hn;
        }
        gridbar(tid);

        // ---- stage: kp 0..255 <- h1P[pw1]; kp 256..511 <- h2P[ph2r] ----
        {
            float4* dst4 = (float4*)hs;
            const float4* s1 = (const float4*)(g_h1P + pw1 * 16384);
            const float4* s2 = (const float4*)(g_h2P + ph2r * 16384);
            #pragma unroll
            for (int j = 0; j < 8; j++)  dst4[tid + j * 512] = __ldcg(s1 + tid + j * 512);
            #pragma unroll
            for (int j = 0; j < 8; j++)  dst4[tid + (j + 8) * 512] = __ldcg(s2 + tid + j * 512);
        }
        __syncthreads();

        // ---- layer 2: kp in [oct*64, oct*64+64) over 512 pairs ----
        {
            unsigned long long a0 = 0, a1 = 0, a2 = 0, a3 = 0, a4 = 0, a5 = 0, a6 = 0, a7 = 0;
            const float* wp = wT2 + rg * 16;
            const int kp0 = oct * 64;
            #pragma unroll 8
            for (int kp = kp0; kp < kp0 + 64; kp++) {
                const float* wk = wp + kp * 32;
                ulonglong2 w01 = *(const ulonglong2*)(wk);
                ulonglong2 w23 = *(const ulonglong2*)(wk + 4);
                ulonglong2 w45 = *(const ulonglong2*)(wk + 8);
                ulonglong2 w67 = *(const ulonglong2*)(wk + 12);
                unsigned long long hp = *(const unsigned long long*)(hs + kp * 64 + l * 2);
                FMA2(a0, w01.x, hp); FMA2(a1, w01.y, hp);
                FMA2(a2, w23.x, hp); FMA2(a3, w23.y, hp);
                FMA2(a4, w45.x, hp); FMA2(a5, w45.y, hp);
                FMA2(a6, w67.x, hp); FMA2(a7, w67.y, hp);
            }
            __syncthreads();   // all hs reads done before gpart alias overwrite
            float* gp = gpart + oct * 512 + rg * 8 * 32 + l;
            gp[0] = hadd2(a0);   gp[32] = hadd2(a1);  gp[64] = hadd2(a2);  gp[96] = hadd2(a3);
            gp[128] = hadd2(a4); gp[160] = hadd2(a5); gp[192] = hadd2(a6); gp[224] = hadd2(a7);
        }
        __syncthreads();
        if (tid < 128) {
            float gv[4];
            #pragma unroll
            for (int g = 0; g < 4; g++) {
                int r = ejj * 4 + g;
                float s = bsum[1][r];
                #pragma unroll
                for (int o = 0; o < 8; o++) s += gpart[o * 512 + r * 32 + eb];
                gv[g] = s;
            }
            float cn = sigf(gv[1]) * c2s[ejj][eb] + sigf(gv[0]) * tanhff(gv[2]);
            float hn = sigf(gv[3]) * tanhff(cn);
            c2s[ejj][eb] = cn;
            g_h2P[ph2w * 16384 + (eJ >> 1) * 64 + eb * 2 + (eJ & 1)] = hn;
            int row = t * 32 + eb;
            g_out[(size_t)row * 512 + eJ] = hn;
            g_cat2[(size_t)row * 1024 + 512 + eJ] = hn;
            g_call[(size_t)row * 512 + eJ] = cn;
        }
        __syncthreads();
        // hs kp 0..255 keep h1(t) for next step's layer 1
    }

    if (tid < 128) {
        g_c1f[eb * 512 + eJ] = c1s[ejj][eb];
        g_c2f[eb * 512 + eJ] = c2s[ejj][eb];
    }
}

// ---------------- generic tiled fp32 GEMM (attention path) ----------------
__global__ void k_gemm(int M, int N, int K,
                       const float* __restrict__ A, int lda, long long sA,
                       const float* __restrict__ B, int ldbn, int ldbk, long long sB,
                       const float* __restrict__ bias,
                       float* __restrict__ C, int ldc, long long sC, int act) {
    A += (size_t)blockIdx.z * sA;
    B += (size_t)blockIdx.z * sB;
    C += (size_t)blockIdx.z * sC;
    __shared__ float As[16][64];
    __shared__ float Bs[16][64];
    int tid = threadIdx.x;
    int tx = tid & 15, ty = tid >> 4;
    int m0 = blockIdx.y * 64, n0 = blockIdx.x * 64;
    int ar = tid >> 2, ak = (tid & 3) * 4;
    float acc[4][4] = {};

    for (int k0 = 0; k0 < K; k0 += 16) {
        float4 av = make_float4(0.f, 0.f, 0.f, 0.f);
        if (m0 + ar < M) av = *(const float4*)(A + (size_t)(m0 + ar) * lda + k0 + ak);
        As[ak + 0][ar] = av.x; As[ak + 1][ar] = av.y;
        As[ak + 2][ar] = av.z; As[ak + 3][ar] = av.w;
        if (ldbk == 1) {
            float4 bq = make_float4(0.f, 0.f, 0.f, 0.f);
            if (n0 + ar < N) bq = *(const float4*)(B + (size_t)(n0 + ar) * ldbn + k0 + ak);
            Bs[ak + 0][ar] = bq.x; Bs[ak + 1][ar] = bq.y;
            Bs[ak + 2][ar] = bq.z; Bs[ak + 3][ar] = bq.w;
        } else {
            #pragma unroll
            for (int e = tid; e < 1024; e += 256) {
                int n = e & 63, kk = e >> 6;
                float v = 0.f;
                if (n0 + n < N) v = B[(size_t)(n0 + n) * ldbn + (size_t)(k0 + kk) * ldbk];
                Bs[kk][n] = v;
            }
        }
        __syncthreads();
        #pragma unroll
        for (int kk = 0; kk < 16; kk++) {
            float4 a = *(const float4*)(&As[kk][ty * 4]);
            float4 bq = *(const float4*)(&Bs[kk][tx * 4]);
            acc[0][0] += a.x * bq.x; acc[0][1] += a.x * bq.y; acc[0][2] += a.x * bq.z; acc[0][3] += a.x * bq.w;
            acc[1][0] += a.y * bq.x; acc[1][1] += a.y * bq.y; acc[1][2] += a.y * bq.z; acc[1][3] += a.y * bq.w;
            acc[2][0] += a.z * bq.x; acc[2][1] += a.z * bq.y; acc[2][2] += a.z * bq.z; acc[2][3] += a.z * bq.w;
            acc[3][0] += a.w * bq.x; acc[3][1] += a.w * bq.y; acc[3][2] += a.w * bq.z; acc[3][3] += a.w * bq.w;
        }
        __syncthreads();
    }

    #pragma unroll
    for (int i = 0; i < 4; i++) {
        int m = m0 + ty * 4 + i;
        if (m >= M) continue;
        #pragma unroll
        for (int jc = 0; jc < 4; jc++) {
            int n = n0 + tx * 4 + jc;
            if (n >= N) continue;
            float v = acc[i][jc];
            if (bias) v += bias[n];
            if (act == 1) v = tanhf(v);
            C[(size_t)m * ldc + n] = v;
        }
    }
}

// ---------------- generalized bf16 HMMA GEMM (register prefetch, static smem) ----------------
#define VPAD 72

__global__ void __launch_bounds__(256) k_hgemm(
    const __nv_bfloat16* __restrict__ A,   // [M, K] bf16 row-major
    const __nv_bfloat16* __restrict__ B,   // [>=nbound, K] bf16 row-major
    const float* __restrict__ bias,
    float* __restrict__ C,                 // [M, ldc] fp32 (unused when eout set)
    int K, int ldc, int nbound, int act,
    float* __restrict__ sumpart, int nbx,
    __nv_bfloat16* __restrict__ bf16out,   // optional bf16 copy of C
    __half* __restrict__ eout)             // optional: store exp(v) as fp16 (half2), skip C
{
    __shared__ __nv_bfloat16 As[128 * VPAD];
    __shared__ __nv_bfloat16 Bs[128 * VPAD];
    __shared__ float srow[128 * 17];

    const int tid = threadIdx.x;
    const int wid = tid >> 5, lane = tid & 31;
    const int m0 = blockIdx.y * 128, n0 = blockIdx.x * 128;
    const int wr = wid >> 2, wc = wid & 3;

    float acc[4][4][4] = {};
    const uint32_t sA = smem_u32(As), sB = smem_u32(Bs);
    const int nkc = K >> 6;

    uint4 pa[4], pb[4];
    #pragma unroll
    for (int it = 0; it < 4; it++) {
        int idx = tid + it * 256;
        int row = idx >> 3, qv = idx & 7;
        pa[it] = *(const uint4*)(A + (size_t)(m0 + row) * K + qv * 8);
        int n = n0 + row;
        pb[it] = make_uint4(0u, 0u, 0u, 0u);
        if (n < nbound) pb[it] = *(const uint4*)(B + (size_t)n * K + qv * 8);
    }

    for (int kc = 0; kc < nkc; kc++) {
        #pragma unroll
        for (int it = 0; it < 4; it++) {
            int idx = tid + it * 256;
            int row = idx >> 3, qv = idx & 7;
            *(uint4*)(As + row * VPAD + qv * 8) = pa[it];
            *(uint4*)(Bs + row * VPAD + qv * 8) = pb[it];
        }
        __syncthreads();
        if (kc + 1 < nkc) {
            #pragma unroll
            for (int it = 0; it < 4; it++) {
                int idx = tid + it * 256;
                int row = idx >> 3, qv = idx & 7;
                pa[it] = *(const uint4*)(A + (size_t)(m0 + row) * K + (kc + 1) * 64 + qv * 8);
                int n = n0 + row;
                pb[it] = make_uint4(0u, 0u, 0u, 0u);
                if (n < nbound) pb[it] = *(const uint4*)(B + (size_t)n * K + (kc + 1) * 64 + qv * 8);
            }
        }

        #pragma unroll
        for (int ks = 0; ks < 4; ks++) {
            uint32_t af[4][4];
            uint32_t bf[4][2];
            #pragma unroll
            for (int fm = 0; fm < 4; fm++) {
                int row = wr * 64 + fm * 16 + (lane & 15);
                int col = ks * 16 + ((lane >> 4) << 3);
                uint32_t addr = sA + (row * VPAD + col) * 2;
                asm volatile("ldmatrix.sync.aligned.m8n8.x4.shared.b16 {%0,%1,%2,%3}, [%4];"
                    : "=r"(af[fm][0]), "=r"(af[fm][1]), "=r"(af[fm][2]), "=r"(af[fm][3])
                    : "r"(addr));
            }
            #pragma unroll
            for (int fn = 0; fn < 4; fn++) {
                int row = wc * 32 + fn * 8 + (lane & 7);
                int col = ks * 16 + (((lane >> 3) & 1) << 3);
                uint32_t addr = sB + (row * VPAD + col) * 2;
                asm volatile("ldmatrix.sync.aligned.m8n8.x2.shared.b16 {%0,%1}, [%2];"
                    : "=r"(bf[fn][0]), "=r"(bf[fn][1]) : "r"(addr));
            }
            #pragma unroll
            for (int fm = 0; fm < 4; fm++) {
                #pragma unroll
                for (int fn = 0; fn < 4; fn++) {
                    asm volatile(
                        "mma.sync.aligned.m16n8k16.row.col.f32.bf16.bf16.f32 "
                        "{%0,%1,%2,%3}, {%4,%5,%6,%7}, {%8,%9}, {%0,%1,%2,%3};"
                        : "+f"(acc[fm][fn][0]), "+f"(acc[fm][fn][1]),
                          "+f"(acc[fm][fn][2]), "+f"(acc[fm][fn][3])
                        : "r"(af[fm][0]), "r"(af[fm][1]), "r"(af[fm][2]), "r"(af[fm][3]),
                          "r"(bf[fn][0]), "r"(bf[fn][1]));
                }
            }
        }
        __syncthreads();
    }

    int gr = lane >> 2, gc = (lane & 3) * 2;
    int slot = wc * 4 + (lane & 3);
    #pragma unroll
    for (int fm = 0; fm < 4; fm++) {
        int lr0 = wr * 64 + fm * 16 + gr;
        int r0 = m0 + lr0;
        float es0 = 0.f, es1 = 0.f;
        if (eout) {
            __half* erow0 = eout + (size_t)r0 * ldc;
            __half* erow1 = eout + (size_t)(r0 + 8) * ldc;
            #pragma unroll
            for (int fn = 0; fn < 4; fn++) {
                int c = n0 + wc * 32 + fn * 8 + gc;
                if (c + 1 < nbound) {
                    float b0 = bias[c], b1 = bias[c + 1];
                    float e0 = __expf(acc[fm][fn][0] + b0);
                    float e1 = __expf(acc[fm][fn][1] + b1);
                    float e2 = __expf(acc[fm][fn][2] + b0);
                    float e3 = __expf(acc[fm][fn][3] + b1);
                    *(__half2*)(erow0 + c) = __floats2half2_rn(e0, e1);
                    *(__half2*)(erow1 + c) = __floats2half2_rn(e2, e3);
                    es0 += e0 + e1;
                    es1 += e2 + e3;
                } else if (c < nbound) {
                    float b0 = bias[c];
                    float e0 = __expf(acc[fm][fn][0] + b0);
                    float e2 = __expf(acc[fm][fn][2] + b0);
                    erow0[c] = __float2half(e0);
                    erow1[c] = __float2half(e2);
                    es0 += e0; es1 += e2;
                }
            }
            srow[lr0 * 17 + slot] = es0;
            srow[(lr0 + 8) * 17 + slot] = es1;
        } else {
            float* crow0 = C + (size_t)r0 * ldc;
            float* crow1 = C + (size_t)(r0 + 8) * ldc;
            #pragma unroll
            for (int fn = 0; fn < 4; fn++) {
                int c = n0 + wc * 32 + fn * 8 + gc;
                if (c + 1 < nbound) {
                    float b0 = bias ? bias[c] : 0.f, b1 = bias ? bias[c + 1] : 0.f;
                    float v0 = acc[fm][fn][0] + b0, v1 = acc[fm][fn][1] + b1;
                    float v2 = acc[fm][fn][2] + b0, v3 = acc[fm][fn][3] + b1;
                    if (act == 1) { v0 = tanhf(v0); v1 = tanhf(v1); v2 = tanhf(v2); v3 = tanhf(v3); }
                    crow0[c] = v0; crow0[c + 1] = v1;
                    crow1[c] = v2; crow1[c + 1] = v3;
                    if (bf16out) {
                        bf16out[(size_t)r0 * ldc + c]           = __float2bfloat16(v0);
                        bf16out[(size_t)r0 * ldc + c + 1]       = __float2bfloat16(v1);
                        bf16out[(size_t)(r0 + 8) * ldc + c]     = __float2bfloat16(v2);
                        bf16out[(size_t)(r0 + 8) * ldc + c + 1] = __float2bfloat16(v3);
                    }
                } else if (c < nbound) {
                    float b0 = bias ? bias[c] : 0.f;
                    float v0 = acc[fm][fn][0] + b0, v2 = acc[fm][fn][2] + b0;
                    if (act == 1) { v0 = tanhf(v0); v2 = tanhf(v2); }
                    crow0[c] = v0; crow1[c] = v2;
                    if (bf16out) {
                        bf16out[(size_t)r0 * ldc + c]       = __float2bfloat16(v0);
                        bf16out[(size_t)(r0 + 8) * ldc + c] = __float2bfloat16(v2);
                    }
                }
            }
        }
    }
    if (sumpart) {
        __syncthreads();
        if (tid < 128) {
            float s = 0.f;
            #pragma unroll
            for (int i = 0; i < 16; i++) s += srow[tid * 17 + i];
            sumpart[(size_t)(m0 + tid) * nbx + blockIdx.x] = s;
        }
    }
}

// ---------------- row-sum reduce -> 1/sum ----------------
__global__ void k_rowsum() {
    int r = blockIdx.x, tid = threadIdx.x;
    __shared__ float red[128];
    float s = 0.f;
    for (int i = tid; i < NBX_V; i += 128) s += g_sumpart[(size_t)r * NBX_V + i];
    red[tid] = s; __syncthreads();
    for (int o = 64; o > 0; o >>= 1) { if (tid < o) red[tid] += red[tid + o]; __syncthreads(); }
    if (tid == 0) g_rinv[r] = 1.f / red[0];
}

// ---------------- attention softmax over S=400 ----------------
__global__ void k_attnsoftmax() {
    int r = blockIdx.x, tid = threadIdx.x;
    __shared__ float vals[SS];
    __shared__ float red[128];
    float m = -1e30f;
    for (int s = tid; s < SS; s += 128) { float v = g_attn[(size_t)r * SS + s]; vals[s] = v; m = fmaxf(m, v); }
    red[tid] = m; __syncthreads();
    for (int o = 64; o > 0; o >>= 1) { if (tid < o) red[tid] = fmaxf(red[tid], red[tid + o]); __syncthreads(); }
    m = red[0]; __syncthreads();
    float sum = 0.f;
    for (int s = tid; s < SS; s += 128) { float e = __expf(vals[s] - m); vals[s] = e; sum += e; }
    red[tid] = sum; __syncthreads();
    for (int o = 64; o > 0; o >>= 1) { if (tid < o) red[tid] += red[tid + o]; __syncthreads(); }
    float inv = 1.f / red[0];
    for (int s = tid; s < SS; s += 128) g_attn[(size_t)r * SS + s] = vals[s] * inv;
}

// ---------------- p_gen ----------------
__global__ void k_pgen(const float* __restrict__ Wg, const float* __restrict__ bg) {
    int warp = threadIdx.x >> 5, lane = threadIdx.x & 31;
    int r = blockIdx.x * 8 + warp;
    float acc = 0.f;
    for (int j = lane; j < 512; j += 32) {
        acc += g_hatt[(size_t)r * HH + j] * Wg[j]
             + g_out [(size_t)r * HH + j] * Wg[512 + j]
             + g_call[(size_t)r * HH + j] * Wg[1024 + j]
             + g_x   [(size_t)r * HH + j] * Wg[1536 + j];
    }
    for (int o = 16; o > 0; o >>= 1) acc += __shfl_down_sync(0xffffffffu, acc, o);
    if (lane == 0) g_pgen[r] = 1.f / (1.f + expf(-(acc + bg[0])));
}

// ---------------- base scores (vectorized fp16 exp-logits: 8 elems/thread) ----------------
__global__ void k_scores(float* __restrict__ out) {
    int r = blockIdx.y;
    int v0 = (blockIdx.x * blockDim.x + threadIdx.x) * 8;
    if (v0 >= EXTV) return;
    float pg = g_pgen[r], inv = g_rinv[r];
    float* orow = out + (size_t)r * EXTV;
    const __half* erow = g_elog + (size_t)r * VV;
    if (v0 + 8 <= VV) {
        uint4 pk = *(const uint4*)(erow + v0);          // 8 halves, 16B aligned
        const __half2* h2p = (const __half2*)&pk;
        float res[8];
        #pragma unroll
        for (int q = 0; q < 4; q++) {
            float2 e = __half22float2(h2p[q]);
            float p0 = e.x * inv, p1 = e.y * inv;
            res[q * 2]     = __logf(p0 * pg + 1e-10f);
            res[q * 2 + 1] = __logf(p1 * pg + 1e-10f);
        }
        #pragma unroll
        for (int q = 0; q < 4; q++)
            *(float2*)(orow + v0 + q * 2) = make_float2(res[q * 2], res[q * 2 + 1]);
    } else {
        float lge = __logf(1e-10f);
        #pragma unroll
        for (int i = 0; i < 8; i++) {
            int v = v0 + i;
            if (v >= EXTV) return;
            float sc;
            if (v < VV) {
                float p = __half2float(erow[v]) * inv;
                sc = __logf(p * pg + 1e-10f);
            } else {
                sc = lge;
            }
            orow[v] = sc;
        }
    }
}

// ---------------- copy fixup (last-write-wins) ----------------
__global__ void k_fixup(const int* __restrict__ src, float* __restrict__ out) {
    int r = blockIdx.x, b = r & 31;
    __shared__ int sid[SS];
    int s = threadIdx.x;
    if (s < SS) sid[s] = src[s * BBATCH + b];
    __syncthreads();
    if (s >= SS) return;
    int v = sid[s];
    for (int s2 = s + 1; s2 < SS; s2++) if (sid[s2] == v) return;
    float pg = g_pgen[r];
    float a = g_attn[(size_t)r * SS + s];
    float pv = 0.f;
    if (v < VV) pv = __half2float(g_elog[(size_t)r * VV + v]) * g_rinv[r];
    out[(size_t)r * EXTV + v] = __logf(pv * pg + a * (1.f - pg) + 1e-10f);
}

// ---------------- final h, c ----------------
__global__ void k_hc(float* __restrict__ out) {
    int i = blockIdx.x * blockDim.x + threadIdx.x;
    float* dst = out + (size_t)TB * EXTV;
    int b = i >> 9, J = i & 511;
    int idx = (J >> 1) * 64 + b * 2 + (J & 1);
    dst[i]          = g_h1P[16384 + idx];   // final h1: parity 1 (t=31)
    dst[16384 + i]  = g_h2P[idx];           // final h2: parity 0
    dst[32768 + i]  = g_c1f[i];
    dst[49152 + i]  = g_c2f[i];
}

// ---------------- launch ----------------
extern "C" void kernel_launch(void* const* d_in, const int* in_sizes, int n_in,
                              void* d_out, int out_size) {
    const int*   ids = (const int*)d_in[0];
    const int*   src = (const int*)d_in[1];
    const float* h0  = (const float*)d_in[2];
    const float* c0  = (const float*)d_in[3];
    const float* ctx = (const float*)d_in[4];
    int base = (in_sizes[5] <= 4) ? 6 : 5;
    const float* emb = (const float*)d_in[base + 0];
    const float* Wih = (const float*)d_in[base + 1];
    const float* bih = (const float*)d_in[base + 2];
    const float* Whh = (const float*)d_in[base + 3];
    const float* bhh = (const float*)d_in[base + 4];
    const float* Wa  = (const float*)d_in[base + 5];
    const float* ba  = (const float*)d_in[base + 6];
    const float* Wo  = (const float*)d_in[base + 7];
    const float* bo  = (const float*)d_in[base + 8];
    const float* Wv  = (const float*)d_in[base + 9];
    const float* bv  = (const float*)d_in[base + 10];
    const float* Wg  = (const float*)d_in[base + 11];
    const float* bg  = (const float*)d_in[base + 12];
    float* out = (float*)d_out;

    float *px, *pxw, *pout, *pgamma, *pattn, *pcat2, *phatt, *psum;
    __half* pelog;
    __nv_bfloat16 *phattb, *pwvb, *pwi1p, *pxp, *pcat2p, *pwop;
    cudaGetSymbolAddress((void**)&px,      g_x);
    cudaGetSymbolAddress((void**)&pxw,     g_xw);
    cudaGetSymbolAddress((void**)&pout,    g_out);
    cudaGetSymbolAddress((void**)&pgamma,  g_gamma);
    cudaGetSymbolAddress((void**)&pattn,   g_attn);
    cudaGetSymbolAddress((void**)&pcat2,   g_cat2);
    cudaGetSymbolAddress((void**)&phatt,   g_hatt);
    cudaGetSymbolAddress((void**)&pelog,   g_elog);
    cudaGetSymbolAddress((void**)&psum,    g_sumpart);
    cudaGetSymbolAddress((void**)&phattb,  g_hattb);
    cudaGetSymbolAddress((void**)&pwvb,    g_wvb);
    cudaGetSymbolAddress((void**)&pwi1p,   g_wi1p);
    cudaGetSymbolAddress((void**)&pxp,     g_xp);
    cudaGetSymbolAddress((void**)&pcat2p,  g_cat2p);
    cudaGetSymbolAddress((void**)&pwop,    g_wop);

    const int SMEM_PERSIST = (512 * 16 + 1024 * 16 + 1024 * 32) * 4;  // 229376 B
    cudaFuncSetAttribute(k_persist, cudaFuncAttributeMaxDynamicSharedMemorySize, SMEM_PERSIST);

    // 1. embedding + weight converts/packs + h0 transpose
    k_embed<<<512, 256>>>(ids, emb);
    k_cvt<<<25000, 256>>>(Wv, pwvb, VV * HH / 4);
    k_pack3<<<4096, 256>>>(Wih, pwi1p, HH, 2048 * HH, 0);      // [hi|hi|lo]
    k_pack3<<<2048, 256>>>(px, pxp, HH, TB * HH, 1);           // [hi|lo|hi]
    k_pack3<<<2048, 256>>>(Wo, pwop, 2 * HH, HH * 2 * HH, 0);  // [hi|hi|lo]
    k_tr<<<64, 512>>>(h0);

    // 2. xw hoist via split-bf16 HMMA (K=1536)
    k_hgemm<<<dim3(8, 16), 256>>>(pwi1p, pxp, nullptr, pxw,
                                  3 * HH, TB, TB, 0, nullptr, 0, nullptr, nullptr);

    // 3. persistent 2-layer LSTM (flat atomic gridbar, xw prefetch)
    k_persist<<<NBLK, 512, SMEM_PERSIST>>>(Whh, Wih + 2048 * 512, Whh + 2048 * 512,
                                           bih, bhh, c0);

    // 4. gamma = out @ Wa^T + ba (fp32)
    k_gemm<<<dim3(8, 16, 1), 256>>>(TB, HH, HH, pout, HH, 0,
                                    Wa, HH, 1, 0, ba, pgamma, HH, 0, 0);

    // 5. attn logits per b: gamma @ contexts[b]^T (fp32)
    k_gemm<<<dim3(7, 1, 32), 256>>>(BBATCH, SS, HH,
                                    pgamma, BBATCH * HH, HH,
                                    ctx, HH, 1, (long long)SS * HH,
                                    nullptr, pattn, BBATCH * SS, SS, 0);

    // 6. softmax over s
    k_attnsoftmax<<<TB, 128>>>();

    // 7. c_t = attn @ contexts[b] (fp32)
    k_gemm<<<dim3(8, 1, 32), 256>>>(BBATCH, HH, SS,
                                    pattn, BBATCH * SS, SS,
                                    ctx, 1, HH, (long long)SS * HH,
                                    nullptr, pcat2, BBATCH * 2 * HH, 2 * HH, 0);

    // 8. h_att = tanh(cat2 @ Wo^T + bo) via split-bf16 HMMA; bf16 copy fused
    k_pack3<<<4096, 256>>>(pcat2, pcat2p, 2 * HH, TB * 2 * HH, 1);  // [hi|lo|hi]
    k_hgemm<<<dim3(4, 8), 256>>>(pcat2p, pwop, bo, phatt,
                                 3 * 2 * HH, HH, HH, 1, nullptr, 0, phattb, nullptr);

    // 9. p_gen
    k_pgen<<<128, 256>>>(Wg, bg);

    // 10. vocab: fused exp(logits)->fp16 (half2 stores) + row-sum partials
    k_hgemm<<<dim3(NBX_V, 8), 256>>>(phattb, pwvb, bv, nullptr,
                                     HH, VV, VV, 0, psum, NBX_V, nullptr, pelog);
    k_rowsum<<<TB, 128>>>();

    // 11. scores (vectorized) + copy fixup
    k_scores<<<dim3(25, TB, 1), 256>>>(out);
    k_fixup<<<TB, 512>>>(src, out);

    // 12. final h, c
    k_hc<<<64, 256>>>(out);
}

// round 17
// speedup vs baseline: 1.0434x; 1.0105x over previous
#include <cuda_runtime.h>
#include <cuda_bf16.h>
#include <cstdint>
#include <math.h>

#define TT 32
#define BBATCH 32
#define HH 512
#define SS 400
#define VV 50000
#define EXTV 50050
#define TB 1024  // TT*BBATCH
#define NBLK 128
#define NBX_V 391   // vocab n-tiles

// ---------------- scratch (static device arrays; no allocation) ----------------
__device__ float g_x[TB * HH];
__device__ float g_xw[2048 * TB];       // W_ih1 @ x^T : [gate_row][t*32+b]
__device__ float g_out[TB * HH];
__device__ float g_call[TB * HH];
__device__ float g_h1P[2 * HH * BBATCH];  // parity-buffered layer-1 h PAIR-PACKED [p][J/2][b][2]
__device__ float g_h2P[2 * HH * BBATCH];
__device__ float g_c1f[BBATCH * HH];
__device__ float g_c2f[BBATCH * HH];
__device__ float g_gamma[TB * HH];
__device__ float g_attn[TB * SS];
__device__ float g_cat2[TB * 2 * HH];
__device__ float g_hatt[TB * HH];
__device__ float g_pgen[TB];
__device__ float g_rinv[TB];
__device__ float g_sumpart[TB * NBX_V];
__device__ float g_logits[(size_t)TB * VV];          // 200 MB
__device__ __nv_bfloat16 g_hattb[TB * HH];
__device__ __nv_bfloat16 g_wvb[(size_t)VV * HH];
__device__ __nv_bfloat16 g_wi1p[2048 * 3 * HH];
__device__ __nv_bfloat16 g_xp[TB * 3 * HH];
__device__ __nv_bfloat16 g_cat2p[TB * 3 * 2 * HH];
__device__ __nv_bfloat16 g_wop[HH * 3 * 2 * HH];
__device__ unsigned g_barcnt;
__device__ unsigned g_bargen;

__device__ __forceinline__ uint32_t smem_u32(const void* p) {
    uint32_t a;
    asm("{ .reg .u64 t; cvta.to.shared.u64 t, %1; cvt.u32.u64 %0, t; }" : "=r"(a) : "l"(p));
    return a;
}

#define FMA2(acc, w, h) \
    asm("fma.rn.f32x2 %0, %1, %2, %0;" : "+l"(acc) : "l"(w), "l"(h))

__device__ __forceinline__ float hadd2(unsigned long long a) {
    return __uint_as_float((unsigned)a) + __uint_as_float((unsigned)(a >> 32));
}

// ---------------- embedding ----------------
__global__ void k_embed(const int* __restrict__ ids, const float* __restrict__ emb) {
    int gi = blockIdx.x * blockDim.x + threadIdx.x;
    int r = gi >> 7, e4 = gi & 127;
    int id = ids[r];
    if (id >= VV) id = 1;   // UNK
    float4 v = *(const float4*)(emb + (size_t)id * HH + e4 * 4);
    *(float4*)(g_x + (size_t)r * HH + e4 * 4) = v;
}

// ---------------- fp32 -> bf16 convert ----------------
__global__ void k_cvt(const float* __restrict__ src, __nv_bfloat16* __restrict__ dst, int n4) {
    int i = blockIdx.x * blockDim.x + threadIdx.x;
    if (i >= n4) return;
    float4 v = ((const float4*)src)[i];
    __nv_bfloat162 a = __floats2bfloat162_rn(v.x, v.y);
    __nv_bfloat162 b = __floats2bfloat162_rn(v.z, v.w);
    ((__nv_bfloat162*)dst)[i * 2]     = a;
    ((__nv_bfloat162*)dst)[i * 2 + 1] = b;
}

// ---------------- split-bf16 pack: mode 0 -> [hi|hi|lo], mode 1 -> [hi|lo|hi] ----------------
__global__ void k_pack3(const float* __restrict__ src, __nv_bfloat16* __restrict__ dst,
                        int K, int total, int mode) {
    int i = blockIdx.x * blockDim.x + threadIdx.x;
    if (i >= total) return;
    int r = i / K, k = i - r * K;
    float v = src[i];
    __nv_bfloat16 hi = __float2bfloat16(v);
    __nv_bfloat16 lo = __float2bfloat16(v - __bfloat162float(hi));
    __nv_bfloat16* row = dst + (size_t)r * 3 * K;
    row[k] = hi;
    if (mode == 0) { row[K + k] = hi; row[2 * K + k] = lo; }
    else           { row[K + k] = lo; row[2 * K + k] = hi; }
}

// ---------------- transpose h0 into pair-packed parity buffers ----------------
__global__ void k_tr(const float* __restrict__ h0) {
    int i = blockIdx.x * blockDim.x + threadIdx.x;
    if (i >= 32768) return;
    int layer = i >> 14, rem = i & 16383;
    int J = rem >> 5, b = rem & 31;
    float v = h0[layer * 16384 + b * 512 + J];
    int idx = (J >> 1) * 64 + b * 2 + (J & 1);
    if (layer) g_h2P[idx] = v;            // parity 0
    else       g_h1P[16384 + idx] = v;    // parity 1
}

// ---------------- persistent 2-layer LSTM (flat atomic gridbar, xw prefetch) ----------------
__device__ __forceinline__ float sigf(float x) { return 1.0f / (1.0f + __expf(-x)); }
__device__ __forceinline__ float tanhff(float x) { return 1.0f - 2.0f / (__expf(2.0f * x) + 1.0f); }

__device__ __forceinline__ void gridbar(int tid) {
    __syncthreads();
    if (tid == 0) {
        __threadfence();
        unsigned gen = *(volatile unsigned*)&g_bargen;
        unsigned old = atomicAdd(&g_barcnt, 1u);
        if (old == NBLK - 1) {
            atomicExch(&g_barcnt, 0u);
            __threadfence();
            atomicAdd(&g_bargen, 1u);
        } else {
            while (*(volatile unsigned*)&g_bargen == gen) { }
        }
        __threadfence();
    }
    __syncthreads();
}

// smem weight layout: [kp][16 rows][2] floats. h layout: [kp][32 b][2] floats.
__global__ void __launch_bounds__(512, 1) k_persist(
    const float* __restrict__ Whh1, const float* __restrict__ Wih2,
    const float* __restrict__ Whh2,
    const float* __restrict__ bih, const float* __restrict__ bhh,
    const float* __restrict__ c0)
{
    extern __shared__ float sm[];
    float* wT1 = sm;                         // [256 kp][16][2]   32 KB
    float* wT2 = sm + 512 * 16;              // [512 kp][16][2]   64 KB
    float* hs  = sm + 512 * 16 + 1024 * 16;  // [512 kp][32][2]  128 KB
    float* gpart = hs + 16384;               // alias kp 256..319 (layer-2-only region)

    __shared__ float c1s[4][32], c2s[4][32], bsum[2][16];

    const int tid = threadIdx.x;
    const int bid = blockIdx.x;
    const int w = tid >> 5, l = tid & 31;
    const int rg = w >> 3;          // 0..1
    const int oct = w & 7;          // 0..7
    const int ejj = tid >> 5, eb = tid & 31, eJ = bid * 4 + ejj;  // epilogue coords (tid<128)

    #pragma unroll 1
    for (int r = 0; r < 16; r++) {
        int g = r & 3, jj = r >> 2;
        int G = g * 512 + bid * 4 + jj;
        int k = tid;  // 0..511
        int kp = k >> 1, kq = k & 1;
        wT1[kp * 32 + r * 2 + kq]          = Whh1[(size_t)G * 512 + k];
        wT2[kp * 32 + r * 2 + kq]          = Wih2[(size_t)G * 512 + k];
        wT2[(256 + kp) * 32 + r * 2 + kq]  = Whh2[(size_t)G * 512 + k];
    }
    if (tid < 32) {
        int layer = tid >> 4, r = tid & 15;
        int g = r & 3, jj = r >> 2;
        int G = layer * 2048 + g * 512 + bid * 4 + jj;
        bsum[layer][r] = bih[G] + bhh[G];
    }
    if (tid < 128) {
        c1s[ejj][eb] = c0[eb * 512 + eJ];
        c2s[ejj][eb] = c0[16384 + eb * 512 + eJ];
    }
    {
        float4* dst4 = (float4*)hs;
        const float4* s1 = (const float4*)(g_h1P + 16384);
        #pragma unroll
        for (int j = 0; j < 8; j++) dst4[tid + j * 512] = s1[tid + j * 512];
    }
    __syncthreads();

    for (int t = 0; t < TT; t++) {
        const int pw1 = t & 1;
        const int ph2r = t & 1;
        const int ph2w = (t & 1) ^ 1;

        // prefetch xw for this step's layer-1 epilogue (xw is constant -> safe)
        float xwreg[4];
        if (tid < 128) {
            #pragma unroll
            for (int g = 0; g < 4; g++)
                xwreg[g] = __ldg(&g_xw[(size_t)(g * 512 + eJ) * 1024 + t * 32 + eb]);
        }

        // ---- layer 1: kp in [oct*32, oct*32+32) ----
        {
            unsigned long long a0 = 0, a1 = 0, a2 = 0, a3 = 0, a4 = 0, a5 = 0, a6 = 0, a7 = 0;
            const float* wp = wT1 + rg * 16;
            const int kp0 = oct * 32;
            #pragma unroll 8
            for (int kp = kp0; kp < kp0 + 32; kp++) {
                const float* wk = wp + kp * 32;
                ulonglong2 w01 = *(const ulonglong2*)(wk);
                ulonglong2 w23 = *(const ulonglong2*)(wk + 4);
                ulonglong2 w45 = *(const ulonglong2*)(wk + 8);
                ulonglong2 w67 = *(const ulonglong2*)(wk + 12);
                unsigned long long hp = *(const unsigned long long*)(hs + kp * 64 + l * 2);
                FMA2(a0, w01.x, hp); FMA2(a1, w01.y, hp);
                FMA2(a2, w23.x, hp); FMA2(a3, w23.y, hp);
                FMA2(a4, w45.x, hp); FMA2(a5, w45.y, hp);
                FMA2(a6, w67.x, hp); FMA2(a7, w67.y, hp);
            }
            float* gp = gpart + oct * 512 + rg * 8 * 32 + l;
            gp[0] = hadd2(a0);   gp[32] = hadd2(a1);  gp[64] = hadd2(a2);  gp[96] = hadd2(a3);
            gp[128] = hadd2(a4); gp[160] = hadd2(a5); gp[192] = hadd2(a6); gp[224] = hadd2(a7);
        }
        __syncthreads();
        if (tid < 128) {
            float gv[4];
            #pragma unroll
            for (int g = 0; g < 4; g++) {
                int r = ejj * 4 + g;
                float s = bsum[0][r] + xwreg[g];
                #pragma unroll
                for (int o = 0; o < 8; o++) s += gpart[o * 512 + r * 32 + eb];
                gv[g] = s;
            }
            float cn = sigf(gv[1]) * c1s[ejj][eb] + sigf(gv[0]) * tanhff(gv[2]);
            float hn = sigf(gv[3]) * tanhff(cn);
            c1s[ejj][eb] = cn;
            g_h1P[pw1 * 16384 + (eJ >> 1) * 64 + eb * 2 + (eJ & 1)] = hn;
        }
        gridbar(tid);

        // ---- stage: kp 0..255 <- h1P[pw1]; kp 256..511 <- h2P[ph2r] ----
        {
            float4* dst4 = (float4*)hs;
            const float4* s1 = (const float4*)(g_h1P + pw1 * 16384);
            const float4* s2 = (const float4*)(g_h2P + ph2r * 16384);
            #pragma unroll
            for (int j = 0; j < 8; j++)  dst4[tid + j * 512] = __ldcg(s1 + tid + j * 512);
            #pragma unroll
            for (int j = 0; j < 8; j++)  dst4[tid + (j + 8) * 512] = __ldcg(s2 + tid + j * 512);
        }
        __syncthreads();

        // ---- layer 2: kp in [oct*64, oct*64+64) over 512 pairs ----
        {
            unsigned long long a0 = 0, a1 = 0, a2 = 0, a3 = 0, a4 = 0, a5 = 0, a6 = 0, a7 = 0;
            const float* wp = wT2 + rg * 16;
            const int kp0 = oct * 64;
            #pragma unroll 8
            for (int kp = kp0; kp < kp0 + 64; kp++) {
                const float* wk = wp + kp * 32;
                ulonglong2 w01 = *(const ulonglong2*)(wk);
                ulonglong2 w23 = *(const ulonglong2*)(wk + 4);
                ulonglong2 w45 = *(const ulonglong2*)(wk + 8);
                ulonglong2 w67 = *(const ulonglong2*)(wk + 12);
                unsigned long long hp = *(const unsigned long long*)(hs + kp * 64 + l * 2);
                FMA2(a0, w01.x, hp); FMA2(a1, w01.y, hp);
                FMA2(a2, w23.x, hp); FMA2(a3, w23.y, hp);
                FMA2(a4, w45.x, hp); FMA2(a5, w45.y, hp);
                FMA2(a6, w67.x, hp); FMA2(a7, w67.y, hp);
            }
            __syncthreads();   // all hs reads done before gpart alias overwrite
            float* gp = gpart + oct * 512 + rg * 8 * 32 + l;
            gp[0] = hadd2(a0);   gp[32] = hadd2(a1);  gp[64] = hadd2(a2);  gp[96] = hadd2(a3);
            gp[128] = hadd2(a4); gp[160] = hadd2(a5); gp[192] = hadd2(a6); gp[224] = hadd2(a7);
        }
        __syncthreads();
        if (tid < 128) {
            float gv[4];
            #pragma unroll
            for (int g = 0; g < 4; g++) {
                int r = ejj * 4 + g;
                float s = bsum[1][r];
                #pragma unroll
                for (int o = 0; o < 8; o++) s += gpart[o * 512 + r * 32 + eb];
                gv[g] = s;
            }
            float cn = sigf(gv[1]) * c2s[ejj][eb] + sigf(gv[0]) * tanhff(gv[2]);
            float hn = sigf(gv[3]) * tanhff(cn);
            c2s[ejj][eb] = cn;
            g_h2P[ph2w * 16384 + (eJ >> 1) * 64 + eb * 2 + (eJ & 1)] = hn;
            int row = t * 32 + eb;
            g_out[(size_t)row * 512 + eJ] = hn;
            g_cat2[(size_t)row * 1024 + 512 + eJ] = hn;
            g_call[(size_t)row * 512 + eJ] = cn;
        }
        __syncthreads();
        // hs kp 0..255 keep h1(t) for next step's layer 1
    }

    if (tid < 128) {
        g_c1f[eb * 512 + eJ] = c1s[ejj][eb];
        g_c2f[eb * 512 + eJ] = c2s[ejj][eb];
    }
}

// ---------------- generic tiled fp32 GEMM (attention path) ----------------
__global__ void k_gemm(int M, int N, int K,
                       const float* __restrict__ A, int lda, long long sA,
                       const float* __restrict__ B, int ldbn, int ldbk, long long sB,
                       const float* __restrict__ bias,
                       float* __restrict__ C, int ldc, long long sC, int act) {
    A += (size_t)blockIdx.z * sA;
    B += (size_t)blockIdx.z * sB;
    C += (size_t)blockIdx.z * sC;
    __shared__ float As[16][64];
    __shared__ float Bs[16][64];
    int tid = threadIdx.x;
    int tx = tid & 15, ty = tid >> 4;
    int m0 = blockIdx.y * 64, n0 = blockIdx.x * 64;
    int ar = tid >> 2, ak = (tid & 3) * 4;
    float acc[4][4] = {};

    for (int k0 = 0; k0 < K; k0 += 16) {
        float4 av = make_float4(0.f, 0.f, 0.f, 0.f);
        if (m0 + ar < M) av = *(const float4*)(A + (size_t)(m0 + ar) * lda + k0 + ak);
        As[ak + 0][ar] = av.x; As[ak + 1][ar] = av.y;
        As[ak + 2][ar] = av.z; As[ak + 3][ar] = av.w;
        if (ldbk == 1) {
            float4 bq = make_float4(0.f, 0.f, 0.f, 0.f);
            if (n0 + ar < N) bq = *(const float4*)(B + (size_t)(n0 + ar) * ldbn + k0 + ak);
            Bs[ak + 0][ar] = bq.x; Bs[ak + 1][ar] = bq.y;
            Bs[ak + 2][ar] = bq.z; Bs[ak + 3][ar] = bq.w;
        } else {
            #pragma unroll
            for (int e = tid; e < 1024; e += 256) {
                int n = e & 63, kk = e >> 6;
                float v = 0.f;
                if (n0 + n < N) v = B[(size_t)(n0 + n) * ldbn + (size_t)(k0 + kk) * ldbk];
                Bs[kk][n] = v;
            }
        }
        __syncthreads();
        #pragma unroll
        for (int kk = 0; kk < 16; kk++) {
            float4 a = *(const float4*)(&As[kk][ty * 4]);
            float4 bq = *(const float4*)(&Bs[kk][tx * 4]);
            acc[0][0] += a.x * bq.x; acc[0][1] += a.x * bq.y; acc[0][2] += a.x * bq.z; acc[0][3] += a.x * bq.w;
            acc[1][0] += a.y * bq.x; acc[1][1] += a.y * bq.y; acc[1][2] += a.y * bq.z; acc[1][3] += a.y * bq.w;
            acc[2][0] += a.z * bq.x; acc[2][1] += a.z * bq.y; acc[2][2] += a.z * bq.z; acc[2][3] += a.z * bq.w;
            acc[3][0] += a.w * bq.x; acc[3][1] += a.w * bq.y; acc[3][2] += a.w * bq.z; acc[3][3] += a.w * bq.w;
        }
        __syncthreads();
    }

    #pragma unroll
    for (int i = 0; i < 4; i++) {
        int m = m0 + ty * 4 + i;
        if (m >= M) continue;
        #pragma unroll
        for (int jc = 0; jc < 4; jc++) {
            int n = n0 + tx * 4 + jc;
            if (n >= N) continue;
            float v = acc[i][jc];
            if (bias) v += bias[n];
            if (act == 1) v = tanhf(v);
            C[(size_t)m * ldc + n] = v;
        }
    }
}

// ---------------- generalized bf16 HMMA GEMM (m-fastest grid for B-tile L2 reuse) ----------------
// blockIdx.x = m-tile, blockIdx.y = n-tile: all m-blocks of one n run in the
// same wave, so each B tile is fetched once and served from L2 thereafter.
#define VPAD 72

__global__ void __launch_bounds__(256) k_hgemm(
    const __nv_bfloat16* __restrict__ A,   // [M, K] bf16 row-major
    const __nv_bfloat16* __restrict__ B,   // [>=nbound, K] bf16 row-major
    const float* __restrict__ bias,
    float* __restrict__ C,                 // [M, ldc] fp32
    int K, int ldc, int nbound, int act,
    float* __restrict__ sumpart, int nbx,
    __nv_bfloat16* __restrict__ bf16out)   // optional bf16 copy of C
{
    __shared__ __nv_bfloat16 As[128 * VPAD];
    __shared__ __nv_bfloat16 Bs[128 * VPAD];
    __shared__ float srow[128 * 17];

    const int tid = threadIdx.x;
    const int wid = tid >> 5, lane = tid & 31;
    const int m0 = blockIdx.x * 128, n0 = blockIdx.y * 128;   // m-fastest
    const int ntile = blockIdx.y;
    const int wr = wid >> 2, wc = wid & 3;

    float acc[4][4][4] = {};
    const uint32_t sA = smem_u32(As), sB = smem_u32(Bs);
    const int nkc = K >> 6;

    uint4 pa[4], pb[4];
    #pragma unroll
    for (int it = 0; it < 4; it++) {
        int idx = tid + it * 256;
        int row = idx >> 3, qv = idx & 7;
        pa[it] = *(const uint4*)(A + (size_t)(m0 + row) * K + qv * 8);
        int n = n0 + row;
        pb[it] = make_uint4(0u, 0u, 0u, 0u);
        if (n < nbound) pb[it] = *(const uint4*)(B + (size_t)n * K + qv * 8);
    }

    for (int kc = 0; kc < nkc; kc++) {
        #pragma unroll
        for (int it = 0; it < 4; it++) {
            int idx = tid + it * 256;
            int row = idx >> 3, qv = idx & 7;
            *(uint4*)(As + row * VPAD + qv * 8) = pa[it];
            *(uint4*)(Bs + row * VPAD + qv * 8) = pb[it];
        }
        __syncthreads();
        if (kc + 1 < nkc) {
            #pragma unroll
            for (int it = 0; it < 4; it++) {
                int idx = tid + it * 256;
                int row = idx >> 3, qv = idx & 7;
                pa[it] = *(const uint4*)(A + (size_t)(m0 + row) * K + (kc + 1) * 64 + qv * 8);
                int n = n0 + row;
                pb[it] = make_uint4(0u, 0u, 0u, 0u);
                if (n < nbound) pb[it] = *(const uint4*)(B + (size_t)n * K + (kc + 1) * 64 + qv * 8);
            }
        }

        #pragma unroll
        for (int ks = 0; ks < 4; ks++) {
            uint32_t af[4][4];
            uint32_t bf[4][2];
            #pragma unroll
            for (int fm = 0; fm < 4; fm++) {
                int row = wr * 64 + fm * 16 + (lane & 15);
                int col = ks * 16 + ((lane >> 4) << 3);
                uint32_t addr = sA + (row * VPAD + col) * 2;
                asm volatile("ldmatrix.sync.aligned.m8n8.x4.shared.b16 {%0,%1,%2,%3}, [%4];"
                    : "=r"(af[fm][0]), "=r"(af[fm][1]), "=r"(af[fm][2]), "=r"(af[fm][3])
                    : "r"(addr));
            }
            #pragma unroll
            for (int fn = 0; fn < 4; fn++) {
                int row = wc * 32 + fn * 8 + (lane & 7);
                int col = ks * 16 + (((lane >> 3) & 1) << 3);
                uint32_t addr = sB + (row * VPAD + col) * 2;
                asm volatile("ldmatrix.sync.aligned.m8n8.x2.shared.b16 {%0,%1}, [%2];"
                    : "=r"(bf[fn][0]), "=r"(bf[fn][1]) : "r"(addr));
            }
            #pragma unroll
            for (int fm = 0; fm < 4; fm++) {
                #pragma unroll
                for (int fn = 0; fn < 4; fn++) {
                    asm volatile(
                        "mma.sync.aligned.m16n8k16.row.col.f32.bf16.bf16.f32 "
                        "{%0,%1,%2,%3}, {%4,%5,%6,%7}, {%8,%9}, {%0,%1,%2,%3};"
                        : "+f"(acc[fm][fn][0]), "+f"(acc[fm][fn][1]),
                          "+f"(acc[fm][fn][2]), "+f"(acc[fm][fn][3])
                        : "r"(af[fm][0]), "r"(af[fm][1]), "r"(af[fm][2]), "r"(af[fm][3]),
                          "r"(bf[fn][0]), "r"(bf[fn][1]));
                }
            }
        }
        __syncthreads();
    }

    int gr = lane >> 2, gc = (lane & 3) * 2;
    int slot = wc * 4 + (lane & 3);
    #pragma unroll
    for (int fm = 0; fm < 4; fm++) {
        int lr0 = wr * 64 + fm * 16 + gr;
        int r0 = m0 + lr0;
        float* crow0 = C + (size_t)r0 * ldc;
        float* crow1 = C + (size_t)(r0 + 8) * ldc;
        float es0 = 0.f, es1 = 0.f;
        #pragma unroll
        for (int fn = 0; fn < 4; fn++) {
            int c = n0 + wc * 32 + fn * 8 + gc;
            if (c + 1 < nbound) {
                float b0 = bias ? bias[c] : 0.f, b1 = bias ? bias[c + 1] : 0.f;
                float v0 = acc[fm][fn][0] + b0, v1 = acc[fm][fn][1] + b1;
                float v2 = acc[fm][fn][2] + b0, v3 = acc[fm][fn][3] + b1;
                if (act == 1) { v0 = tanhf(v0); v1 = tanhf(v1); v2 = tanhf(v2); v3 = tanhf(v3); }
                crow0[c] = v0; crow0[c + 1] = v1;
                crow1[c] = v2; crow1[c + 1] = v3;
                if (bf16out) {
                    bf16out[(size_t)r0 * ldc + c]           = __float2bfloat16(v0);
                    bf16out[(size_t)r0 * ldc + c + 1]       = __float2bfloat16(v1);
                    bf16out[(size_t)(r0 + 8) * ldc + c]     = __float2bfloat16(v2);
                    bf16out[(size_t)(r0 + 8) * ldc + c + 1] = __float2bfloat16(v3);
                }
                if (sumpart) {
                    es0 += __expf(v0) + __expf(v1);
                    es1 += __expf(v2) + __expf(v3);
                }
            } else if (c < nbound) {
                float b0 = bias ? bias[c] : 0.f;
                float v0 = acc[fm][fn][0] + b0, v2 = acc[fm][fn][2] + b0;
                if (act == 1) { v0 = tanhf(v0); v2 = tanhf(v2); }
                crow0[c] = v0; crow1[c] = v2;
                if (bf16out) {
                    bf16out[(size_t)r0 * ldc + c]       = __float2bfloat16(v0);
                    bf16out[(size_t)(r0 + 8) * ldc + c] = __float2bfloat16(v2);
                }
                if (sumpart) { es0 += __expf(v0); es1 += __expf(v2); }
            }
        }
        if (sumpart) {
            srow[lr0 * 17 + slot] = es0;
            srow[(lr0 + 8) * 17 + slot] = es1;
        }
    }
    if (sumpart) {
        __syncthreads();
        if (tid < 128) {
            float s = 0.f;
            #pragma unroll
            for (int i = 0; i < 16; i++) s += srow[tid * 17 + i];
            sumpart[(size_t)(m0 + tid) * nbx + ntile] = s;
        }
    }
}

// ---------------- row-sum reduce -> 1/sum ----------------
__global__ void k_rowsum() {
    int r = blockIdx.x, tid = threadIdx.x;
    __shared__ float red[128];
    float s = 0.f;
    for (int i = tid; i < NBX_V; i += 128) s += g_sumpart[(size_t)r * NBX_V + i];
    red[tid] = s; __syncthreads();
    for (int o = 64; o > 0; o >>= 1) { if (tid < o) red[tid] += red[tid + o]; __syncthreads(); }
    if (tid == 0) g_rinv[r] = 1.f / red[0];
}

// ---------------- attention softmax over S=400 ----------------
__global__ void k_attnsoftmax() {
    int r = blockIdx.x, tid = threadIdx.x;
    __shared__ float vals[SS];
    __shared__ float red[128];
    float m = -1e30f;
    for (int s = tid; s < SS; s += 128) { float v = g_attn[(size_t)r * SS + s]; vals[s] = v; m = fmaxf(m, v); }
    red[tid] = m; __syncthreads();
    for (int o = 64; o > 0; o >>= 1) { if (tid < o) red[tid] = fmaxf(red[tid], red[tid + o]); __syncthreads(); }
    m = red[0]; __syncthreads();
    float sum = 0.f;
    for (int s = tid; s < SS; s += 128) { float e = __expf(vals[s] - m); vals[s] = e; sum += e; }
    red[tid] = sum; __syncthreads();
    for (int o = 64; o > 0; o >>= 1) { if (tid < o) red[tid] += red[tid + o]; __syncthreads(); }
    float inv = 1.f / red[0];
    for (int s = tid; s < SS; s += 128) g_attn[(size_t)r * SS + s] = vals[s] * inv;
}

// ---------------- p_gen ----------------
__global__ void k_pgen(const float* __restrict__ Wg, const float* __restrict__ bg) {
    int warp = threadIdx.x >> 5, lane = threadIdx.x & 31;
    int r = blockIdx.x * 8 + warp;
    float acc = 0.f;
    for (int j = lane; j < 512; j += 32) {
        acc += g_hatt[(size_t)r * HH + j] * Wg[j]
             + g_out [(size_t)r * HH + j] * Wg[512 + j]
             + g_call[(size_t)r * HH + j] * Wg[1024 + j]
             + g_x   [(size_t)r * HH + j] * Wg[1536 + j];
    }
    for (int o = 16; o > 0; o >>= 1) acc += __shfl_down_sync(0xffffffffu, acc, o);
    if (lane == 0) g_pgen[r] = 1.f / (1.f + expf(-(acc + bg[0])));
}

// ---------------- base scores ----------------
__global__ void k_scores(float* __restrict__ out) {
    int r = blockIdx.y;
    int v0 = (blockIdx.x * blockDim.x + threadIdx.x) * 4;
    float pg = g_pgen[r], inv = g_rinv[r];
    float* orow = out + (size_t)r * EXTV;
    const float* lrow = g_logits + (size_t)r * VV;
    #pragma unroll
    for (int i = 0; i < 4; i++) {
        int v = v0 + i;
        if (v >= EXTV) return;
        float sc;
        if (v < VV) {
            float p = __expf(lrow[v]) * inv;
            sc = __logf(p * pg + 1e-10f);
        } else {
            sc = __logf(1e-10f);
        }
        orow[v] = sc;
    }
}

// ---------------- copy fixup (last-write-wins) ----------------
__global__ void k_fixup(const int* __restrict__ src, float* __restrict__ out) {
    int r = blockIdx.x, b = r & 31;
    __shared__ int sid[SS];
    int s = threadIdx.x;
    if (s < SS) sid[s] = src[s * BBATCH + b];
    __syncthreads();
    if (s >= SS) return;
    int v = sid[s];
    for (int s2 = s + 1; s2 < SS; s2++) if (sid[s2] == v) return;
    float pg = g_pgen[r];
    float a = g_attn[(size_t)r * SS + s];
    float pv = 0.f;
    if (v < VV) pv = __expf(g_logits[(size_t)r * VV + v]) * g_rinv[r];
    out[(size_t)r * EXTV + v] = __logf(pv * pg + a * (1.f - pg) + 1e-10f);
}

// ---------------- final h, c ----------------
__global__ void k_hc(float* __restrict__ out) {
    int i = blockIdx.x * blockDim.x + threadIdx.x;
    float* dst = out + (size_t)TB * EXTV;
    int b = i >> 9, J = i & 511;
    int idx = (J >> 1) * 64 + b * 2 + (J & 1);
    dst[i]          = g_h1P[16384 + idx];   // final h1: parity 1 (t=31)
    dst[16384 + i]  = g_h2P[idx];           // final h2: parity 0
    dst[32768 + i]  = g_c1f[i];
    dst[49152 + i]  = g_c2f[i];
}

// ---------------- launch ----------------
extern "C" void kernel_launch(void* const* d_in, const int* in_sizes, int n_in,
                              void* d_out, int out_size) {
    const int*   ids = (const int*)d_in[0];
    const int*   src = (const int*)d_in[1];
    const float* h0  = (const float*)d_in[2];
    const float* c0  = (const float*)d_in[3];
    const float* ctx = (const float*)d_in[4];
    int base = (in_sizes[5] <= 4) ? 6 : 5;
    const float* emb = (const float*)d_in[base + 0];
    const float* Wih = (const float*)d_in[base + 1];
    const float* bih = (const float*)d_in[base + 2];
    const float* Whh = (const float*)d_in[base + 3];
    const float* bhh = (const float*)d_in[base + 4];
    const float* Wa  = (const float*)d_in[base + 5];
    const float* ba  = (const float*)d_in[base + 6];
    const float* Wo  = (const float*)d_in[base + 7];
    const float* bo  = (const float*)d_in[base + 8];
    const float* Wv  = (const float*)d_in[base + 9];
    const float* bv  = (const float*)d_in[base + 10];
    const float* Wg  = (const float*)d_in[base + 11];
    const float* bg  = (const float*)d_in[base + 12];
    float* out = (float*)d_out;

    float *px, *pxw, *pout, *pgamma, *pattn, *pcat2, *phatt, *plogits, *psum;
    __nv_bfloat16 *phattb, *pwvb, *pwi1p, *pxp, *pcat2p, *pwop;
    cudaGetSymbolAddress((void**)&px,      g_x);
    cudaGetSymbolAddress((void**)&pxw,     g_xw);
    cudaGetSymbolAddress((void**)&pout,    g_out);
    cudaGetSymbolAddress((void**)&pgamma,  g_gamma);
    cudaGetSymbolAddress((void**)&pattn,   g_attn);
    cudaGetSymbolAddress((void**)&pcat2,   g_cat2);
    cudaGetSymbolAddress((void**)&phatt,   g_hatt);
    cudaGetSymbolAddress((void**)&plogits, g_logits);
    cudaGetSymbolAddress((void**)&psum,    g_sumpart);
    cudaGetSymbolAddress((void**)&phattb,  g_hattb);
    cudaGetSymbolAddress((void**)&pwvb,    g_wvb);
    cudaGetSymbolAddress((void**)&pwi1p,   g_wi1p);
    cudaGetSymbolAddress((void**)&pxp,     g_xp);
    cudaGetSymbolAddress((void**)&pcat2p,  g_cat2p);
    cudaGetSymbolAddress((void**)&pwop,    g_wop);

    const int SMEM_PERSIST = (512 * 16 + 1024 * 16 + 1024 * 32) * 4;  // 229376 B
    cudaFuncSetAttribute(k_persist, cudaFuncAttributeMaxDynamicSharedMemorySize, SMEM_PERSIST);

    // 1. embedding + weight converts/packs + h0 transpose
    k_embed<<<512, 256>>>(ids, emb);
    k_cvt<<<25000, 256>>>(Wv, pwvb, VV * HH / 4);
    k_pack3<<<4096, 256>>>(Wih, pwi1p, HH, 2048 * HH, 0);      // [hi|hi|lo]
    k_pack3<<<2048, 256>>>(px, pxp, HH, TB * HH, 1);           // [hi|lo|hi]
    k_pack3<<<2048, 256>>>(Wo, pwop, 2 * HH, HH * 2 * HH, 0);  // [hi|hi|lo]
    k_tr<<<64, 512>>>(h0);

    // 2. xw hoist via split-bf16 HMMA (K=1536); grid = (m-tiles, n-tiles)
    k_hgemm<<<dim3(16, 8), 256>>>(pwi1p, pxp, nullptr, pxw,
                                  3 * HH, TB, TB, 0, nullptr, 0, nullptr);

    // 3. persistent 2-layer LSTM (flat atomic gridbar, xw prefetch)
    k_persist<<<NBLK, 512, SMEM_PERSIST>>>(Whh, Wih + 2048 * 512, Whh + 2048 * 512,
                                           bih, bhh, c0);

    // 4. gamma = out @ Wa^T + ba (fp32)
    k_gemm<<<dim3(8, 16, 1), 256>>>(TB, HH, HH, pout, HH, 0,
                                    Wa, HH, 1, 0, ba, pgamma, HH, 0, 0);

    // 5. attn logits per b: gamma @ contexts[b]^T (fp32)
    k_gemm<<<dim3(7, 1, 32), 256>>>(BBATCH, SS, HH,
                                    pgamma, BBATCH * HH, HH,
                                    ctx, HH, 1, (long long)SS * HH,
                                    nullptr, pattn, BBATCH * SS, SS, 0);

    // 6. softmax over s
    k_attnsoftmax<<<TB, 128>>>();

    // 7. c_t = attn @ contexts[b] (fp32)
    k_gemm<<<dim3(8, 1, 32), 256>>>(BBATCH, HH, SS,
                                    pattn, BBATCH * SS, SS,
                                    ctx, 1, HH, (long long)SS * HH,
                                    nullptr, pcat2, BBATCH * 2 * HH, 2 * HH, 0);

    // 8. h_att = tanh(cat2 @ Wo^T + bo) via split-bf16 HMMA; bf16 copy fused
    k_pack3<<<4096, 256>>>(pcat2, pcat2p, 2 * HH, TB * 2 * HH, 1);  // [hi|lo|hi]
    k_hgemm<<<dim3(8, 4), 256>>>(pcat2p, pwop, bo, phatt,
                                 3 * 2 * HH, HH, HH, 1, nullptr, 0, phattb);

    // 9. p_gen
    k_pgen<<<128, 256>>>(Wg, bg);

    // 10. vocab logits via bf16 HMMA with fused exp-sum partials (m-fastest grid)
    k_hgemm<<<dim3(8, NBX_V), 256>>>(phattb, pwvb, bv, plogits,
                                     HH, VV, VV, 0, psum, NBX_V, nullptr);
    k_rowsum<<<TB, 128>>>();

    // 11. scores + copy fixup
    k_scores<<<dim3(49, TB, 1), 256>>>(out);
    k_fixup<<<TB, 512>>>(src, out);

    // 12. final h, c
    k_hc<<<64, 256>>>(out);
}